// round 4
// baseline (speedup 1.0000x reference)
#include <cuda_runtime.h>
#include <cuda_bf16.h>
#include <math.h>
#include <stdint.h>

// ===========================================================================
// AttentionBlock B=8,S=2048,D=512 — mma.sync bf16 3-product fp32-emulation
// R4: 128x256 block tile, 64x64 warp tile, 3-stage cp.async pipeline
// ===========================================================================

#define MTOT (16384 * 512)
__device__ __nv_bfloat16 g_xh[MTOT],  g_xl[MTOT];
__device__ __nv_bfloat16 g_qh[MTOT],  g_ql[MTOT];
__device__ __nv_bfloat16 g_kh[MTOT],  g_kl[MTOT];
__device__ __nv_bfloat16 g_vth[MTOT], g_vtl[MTOT];   // v^T per batch [512][2048]
__device__ __nv_bfloat16 g_onh[MTOT], g_onl[MTOT];
__device__ __nv_bfloat16 g_hh[MTOT],  g_hl[MTOT];    // h1
__device__ __nv_bfloat16 g_h2h[MTOT], g_h2l[MTOT];   // h2
__device__ __nv_bfloat16 g_sh[8LL * 2048 * 2048], g_sl[8LL * 2048 * 2048];
__device__ __nv_bfloat16 g_wth[6 * 512 * 512], g_wtl[6 * 512 * 512]; // W^T [N][K]
__device__ float g_v [MTOT];
__device__ float g_t [MTOT];
__device__ float g_on[MTOT];
__device__ float g_s [8LL * 2048 * 2048];

// ---------------- helpers ----------------
__device__ __forceinline__ uint32_t smem_u32(const void* p) {
    uint32_t a;
    asm("{ .reg .u64 t; cvta.to.shared.u64 t, %1; cvt.u32.u64 %0, t; }"
        : "=r"(a) : "l"(p));
    return a;
}
__device__ __forceinline__ void cpa16(uint32_t dst, const void* src) {
    asm volatile("cp.async.cg.shared.global [%0], [%1], 16;"
                 :: "r"(dst), "l"(src) : "memory");
}
#define CP_COMMIT() asm volatile("cp.async.commit_group;" ::: "memory")
#define CP_WAIT1()  asm volatile("cp.async.wait_group 1;"  ::: "memory")

#define MMA_B16(c, a0, a1, a2, a3, b0, b1)                                    \
    asm volatile("mma.sync.aligned.m16n8k16.row.col.f32.bf16.bf16.f32 "       \
        "{%0,%1,%2,%3}, {%4,%5,%6,%7}, {%8,%9}, {%0,%1,%2,%3};"               \
        : "+f"((c)[0]), "+f"((c)[1]), "+f"((c)[2]), "+f"((c)[3])              \
        : "r"(a0), "r"(a1), "r"(a2), "r"(a3), "r"(b0), "r"(b1))

// ---------------- GEMM ----------------
// Block tile 128(M) x 256(N), BK=32, 8 warps (2x4), warp tile 64x64.
// Planes per stage: Ah(10240B) Al(10240B) Bh(20480B) Bl(20480B) = 61440B
// 3 stages = 184320 B smem, 1 CTA/SM.
#define BKW 20              // padded row stride in words (64B data + 16B pad)
#define A_PLANE_W 2560      // 128 * 20
#define B_PLANE_W 5120      // 256 * 20
#define STAGE_B  61440
#define STAGE_W  15360
#define GEMM_SMEM (3 * STAGE_B)

template <int OUTM>
__global__ __launch_bounds__(256, 1) void mma_gemm(
    const __nv_bfloat16* __restrict__ Ah, const __nv_bfloat16* __restrict__ Al,
    const __nv_bfloat16* __restrict__ Bh, const __nv_bfloat16* __restrict__ Bl,
    const float* __restrict__ bias,
    float* __restrict__ Cf, __nv_bfloat16* __restrict__ Ch, __nv_bfloat16* __restrict__ Cl,
    int N, int K, float alpha,
    long long sA, long long sB, long long sC)
{
    extern __shared__ uint32_t sm[];
    const uint32_t sbase = smem_u32(sm);

    const int bz = blockIdx.z;
    Ah += (long long)bz * sA;  Al += (long long)bz * sA;
    Bh += (long long)bz * sB;  Bl += (long long)bz * sB;

    const int m0 = blockIdx.y * 128;
    const int n0 = blockIdx.x * 256;
    const int tid  = threadIdx.x;
    const int wid  = tid >> 5, lane = tid & 31;
    const int wm   = wid >> 2, wn = wid & 3;      // warp tile: 64 x 64
    const int g    = lane >> 2, t = lane & 3;

    // ---- loader geometry ----
    // A: thread t<128 loads hi row t, t>=128 loads lo row t-128 (4x16B per chunk)
    const int arow = tid & 127;
    const char* gA = (const char*)(((tid < 128) ? Ah : Al) + (long long)(m0 + arow) * K);
    const uint32_t adst = sbase + ((tid < 128) ? 0u : (uint32_t)(A_PLANE_W * 4)) + arow * 80;
    // B: every thread loads hi row tid and lo row tid (4x16B each per chunk)
    const char* gBhp = (const char*)(Bh + (long long)(n0 + tid) * K);
    const char* gBlp = (const char*)(Bl + (long long)(n0 + tid) * K);
    const uint32_t bhdst = sbase + 2 * A_PLANE_W * 4 + tid * 80;
    const uint32_t bldst = sbase + (2 * A_PLANE_W + B_PLANE_W) * 4 + tid * 80;

    float acc[4][8][4];
#pragma unroll
    for (int i = 0; i < 4; i++)
#pragma unroll
        for (int j = 0; j < 8; j++)
#pragma unroll
            for (int e = 0; e < 4; e++) acc[i][j][e] = 0.0f;

    const int NCH = K >> 5;

#define PREFETCH(chv) do {                                                    \
        const uint32_t so = (uint32_t)((chv) % 3) * STAGE_B;                  \
        const long long go = (long long)(chv) * 64;                           \
        cpa16(adst + so,       gA + go);       cpa16(adst + so + 16,  gA + go + 16); \
        cpa16(adst + so + 32,  gA + go + 32);  cpa16(adst + so + 48,  gA + go + 48); \
        cpa16(bhdst + so,      gBhp + go);     cpa16(bhdst + so + 16, gBhp + go + 16); \
        cpa16(bhdst + so + 32, gBhp + go + 32);cpa16(bhdst + so + 48, gBhp + go + 48); \
        cpa16(bldst + so,      gBlp + go);     cpa16(bldst + so + 16, gBlp + go + 16); \
        cpa16(bldst + so + 32, gBlp + go + 32);cpa16(bldst + so + 48, gBlp + go + 48); \
    } while (0)

    PREFETCH(0); CP_COMMIT();
    if (NCH > 1) PREFETCH(1);
    CP_COMMIT();

    for (int ch = 0; ch < NCH; ch++) {
        CP_WAIT1();
        __syncthreads();
        if (ch + 2 < NCH) PREFETCH(ch + 2);
        CP_COMMIT();

        const uint32_t* Sb  = sm + (ch % 3) * STAGE_W;
        const uint32_t* AhS = Sb;
        const uint32_t* AlS = Sb + A_PLANE_W;
        const uint32_t* BhS = Sb + 2 * A_PLANE_W;
        const uint32_t* BlS = Sb + 2 * A_PLANE_W + B_PLANE_W;

        const int abase = (wm * 64 + g) * BKW + t;
        const int bbase = (wn * 64 + g) * BKW + t;

#pragma unroll
        for (int ks = 0; ks < 2; ks++) {
            const int ko = ks * 8;
            uint32_t bh[8][2], bl[8][2];
#pragma unroll
            for (int ni = 0; ni < 8; ni++) {
                const int o = bbase + ni * 160 + ko;
                bh[ni][0] = BhS[o]; bh[ni][1] = BhS[o + 4];
                bl[ni][0] = BlS[o]; bl[ni][1] = BlS[o + 4];
            }
#pragma unroll
            for (int mi = 0; mi < 4; mi++) {
                const int o = abase + mi * 320 + ko;
                const uint32_t ah0 = AhS[o],       ah1 = AhS[o + 160];
                const uint32_t ah2 = AhS[o + 4],   ah3 = AhS[o + 164];
                const uint32_t al0 = AlS[o],       al1 = AlS[o + 160];
                const uint32_t al2 = AlS[o + 4],   al3 = AlS[o + 164];
#pragma unroll
                for (int ni = 0; ni < 8; ni++) {
                    MMA_B16(acc[mi][ni], ah0, ah1, ah2, ah3, bh[ni][0], bh[ni][1]);
                    MMA_B16(acc[mi][ni], al0, al1, al2, al3, bh[ni][0], bh[ni][1]);
                    MMA_B16(acc[mi][ni], ah0, ah1, ah2, ah3, bl[ni][0], bl[ni][1]);
                }
            }
        }
    }

    // ---------------- epilogue ----------------
    float* CfB = Cf + (long long)bz * sC;
    __nv_bfloat16* ChB = Ch + (long long)bz * sC;
    __nv_bfloat16* ClB = Cl + (long long)bz * sC;

#pragma unroll
    for (int mi = 0; mi < 4; mi++) {
#pragma unroll
        for (int ni = 0; ni < 8; ni++) {
            const int r0 = m0 + wm * 64 + mi * 16 + g;
            const int c  = n0 + wn * 64 + ni * 8 + t * 2;
            float v0 = acc[mi][ni][0] * alpha, v1 = acc[mi][ni][1] * alpha;
            float v2 = acc[mi][ni][2] * alpha, v3 = acc[mi][ni][3] * alpha;
            if (bias) {
                const float b0 = bias[c], b1 = bias[c + 1];
                v0 += b0; v1 += b1; v2 += b0; v3 += b1;
            }
            if (OUTM == 0) {
                *(float2*)&CfB[(long long)r0 * N + c]       = make_float2(v0, v1);
                *(float2*)&CfB[(long long)(r0 + 8) * N + c] = make_float2(v2, v3);
            } else {
                __nv_bfloat162 h0 = __floats2bfloat162_rn(v0, v1);
                __nv_bfloat162 l0 = __floats2bfloat162_rn(
                    v0 - __bfloat162float(h0.x), v1 - __bfloat162float(h0.y));
                __nv_bfloat162 h1 = __floats2bfloat162_rn(v2, v3);
                __nv_bfloat162 l1 = __floats2bfloat162_rn(
                    v2 - __bfloat162float(h1.x), v3 - __bfloat162float(h1.y));
                ((__nv_bfloat162*)ChB)[((long long)r0 * N + c) >> 1]       = h0;
                ((__nv_bfloat162*)ClB)[((long long)r0 * N + c) >> 1]       = l0;
                ((__nv_bfloat162*)ChB)[((long long)(r0 + 8) * N + c) >> 1] = h1;
                ((__nv_bfloat162*)ClB)[((long long)(r0 + 8) * N + c) >> 1] = l1;
            }
        }
    }
}

// ---------------- split (fp32 -> bf16 hi/lo) ----------------
__global__ __launch_bounds__(256) void split_kernel(
    const float* __restrict__ in, __nv_bfloat16* __restrict__ oh,
    __nv_bfloat16* __restrict__ ol, int n4)
{
    const int i = blockIdx.x * 256 + threadIdx.x;
    if (i >= n4) return;
    float4 v = ((const float4*)in)[i];
    __nv_bfloat162 h0 = __floats2bfloat162_rn(v.x, v.y);
    __nv_bfloat162 h1 = __floats2bfloat162_rn(v.z, v.w);
    __nv_bfloat162 l0 = __floats2bfloat162_rn(v.x - __bfloat162float(h0.x),
                                              v.y - __bfloat162float(h0.y));
    __nv_bfloat162 l1 = __floats2bfloat162_rn(v.z - __bfloat162float(h1.x),
                                              v.w - __bfloat162float(h1.y));
    ((__nv_bfloat162*)oh)[i * 2]     = h0;
    ((__nv_bfloat162*)oh)[i * 2 + 1] = h1;
    ((__nv_bfloat162*)ol)[i * 2]     = l0;
    ((__nv_bfloat162*)ol)[i * 2 + 1] = l1;
}

// ------------- transpose + split: fp32 [R][C] -> planes [C][R] ----------
__global__ __launch_bounds__(256) void tsplit_kernel(
    const float* __restrict__ in, __nv_bfloat16* __restrict__ oh,
    __nv_bfloat16* __restrict__ ol, int R, int C,
    long long sI, long long sO)
{
    __shared__ float tile[32][33];
    const int z = blockIdx.z;
    in += (long long)z * sI;
    oh += (long long)z * sO;
    ol += (long long)z * sO;
    const int c0 = blockIdx.x * 32, r0 = blockIdx.y * 32;
    const int tx = threadIdx.x & 31, ty = threadIdx.x >> 5;

#pragma unroll
    for (int i = 0; i < 4; i++)
        tile[ty + i * 8][tx] = in[(long long)(r0 + ty + i * 8) * C + c0 + tx];
    __syncthreads();
#pragma unroll
    for (int i = 0; i < 4; i++) {
        const float v = tile[tx][ty + i * 8];
        const __nv_bfloat16 h = __float2bfloat16(v);
        const long long o = (long long)(c0 + ty + i * 8) * R + r0 + tx;
        oh[o] = h;
        ol[o] = __float2bfloat16(v - __bfloat162float(h));
    }
}

// ---------------- softmax (fp32 in, split bf16 out) ----------------
__device__ __forceinline__ float warpMax(float v) {
#pragma unroll
    for (int o = 16; o > 0; o >>= 1) v = fmaxf(v, __shfl_xor_sync(0xffffffffu, v, o));
    return v;
}
__device__ __forceinline__ float warpSum(float v) {
#pragma unroll
    for (int o = 16; o > 0; o >>= 1) v += __shfl_xor_sync(0xffffffffu, v, o);
    return v;
}

__global__ __launch_bounds__(256) void softmax_kernel(
    const float* __restrict__ S, __nv_bfloat16* __restrict__ oh,
    __nv_bfloat16* __restrict__ ol)
{
    const long long base = (long long)blockIdx.x * 2048;
    const float* p = S + base;
    const int tid = threadIdx.x;
    const int lane = tid & 31, wid = tid >> 5;
    __shared__ float sh[8];

    float v[8];
#pragma unroll
    for (int i = 0; i < 8; i++) v[i] = p[tid + i * 256];

    float m = v[0];
#pragma unroll
    for (int i = 1; i < 8; i++) m = fmaxf(m, v[i]);
    m = warpMax(m);
    if (lane == 0) sh[wid] = m;
    __syncthreads();
    m = sh[0];
#pragma unroll
    for (int w = 1; w < 8; w++) m = fmaxf(m, sh[w]);

    float e[8];
    float s = 0.0f;
#pragma unroll
    for (int i = 0; i < 8; i++) { e[i] = __expf(v[i] - m); s += e[i]; }
    s = warpSum(s);
    __syncthreads();
    if (lane == 0) sh[wid] = s;
    __syncthreads();
    float tot = 0.0f;
#pragma unroll
    for (int w = 0; w < 8; w++) tot += sh[w];
    const float inv = 1.0f / tot;

#pragma unroll
    for (int i = 0; i < 8; i++) {
        const float val = e[i] * inv;
        const __nv_bfloat16 h = __float2bfloat16(val);
        oh[base + tid + i * 256] = h;
        ol[base + tid + i * 256] = __float2bfloat16(val - __bfloat162float(h));
    }
}

// ---------------- fused add(+gelu)+LN ----------------
template <int MODE, bool WF32>
__global__ __launch_bounds__(128) void rowln_kernel(
    const float* __restrict__ X, const float* __restrict__ Y,
    const float* __restrict__ g, const float* __restrict__ b,
    float* __restrict__ Of, __nv_bfloat16* __restrict__ Oh,
    __nv_bfloat16* __restrict__ Ol)
{
    const long long row = (long long)blockIdx.x * 512;
    const int tid = threadIdx.x;
    const int lane = tid & 31, wid = tid >> 5;
    __shared__ float s1[4], s2[4];

    float t[4];
    float sum = 0.0f, sq = 0.0f;
#pragma unroll
    for (int i = 0; i < 4; i++) {
        const int c = tid + i * 128;
        float u = X[row + c] + Y[row + c];
        if (MODE == 1) u = 0.5f * u * (1.0f + erff(u * 0.7071067811865476f));
        t[i] = u;
        sum += u;
        sq += u * u;
    }
    sum = warpSum(sum);
    sq = warpSum(sq);
    if (lane == 0) { s1[wid] = sum; s2[wid] = sq; }
    __syncthreads();
    float ts = 0.0f, tq = 0.0f;
#pragma unroll
    for (int w = 0; w < 4; w++) { ts += s1[w]; tq += s2[w]; }
    const float mean = ts * (1.0f / 512.0f);
    const float var = tq * (1.0f / 512.0f) - mean * mean;
    const float inv = rsqrtf(var + 1e-5f);

#pragma unroll
    for (int i = 0; i < 4; i++) {
        const int c = tid + i * 128;
        const float o = (t[i] - mean) * inv * g[c] + b[c];
        if (WF32) Of[row + c] = o;
        const __nv_bfloat16 h = __float2bfloat16(o);
        Oh[row + c] = h;
        Ol[row + c] = __float2bfloat16(o - __bfloat162float(h));
    }
}

// ---------------- host ----------------
template <typename T>
static T* symaddr(const void* sym)
{
    void* p = nullptr;
    cudaGetSymbolAddress(&p, sym);
    return (T*)p;
}

extern "C" void kernel_launch(void* const* d_in, const int* in_sizes, int n_in,
                              void* d_out, int out_size)
{
    const float* x    = (const float*)d_in[0];
    const float* Wq   = (const float*)d_in[1];
    const float* bq   = (const float*)d_in[2];
    const float* Wk   = (const float*)d_in[3];
    const float* bk   = (const float*)d_in[4];
    const float* Wv   = (const float*)d_in[5];
    const float* bv   = (const float*)d_in[6];
    const float* ln0g = (const float*)d_in[7];
    const float* ln0b = (const float*)d_in[8];
    const float* W1   = (const float*)d_in[9];
    const float* b1   = (const float*)d_in[10];
    const float* ln1g = (const float*)d_in[11];
    const float* ln1b = (const float*)d_in[12];
    const float* W2   = (const float*)d_in[13];
    const float* b2   = (const float*)d_in[14];
    const float* ln2g = (const float*)d_in[15];
    const float* ln2b = (const float*)d_in[16];
    const float* W3   = (const float*)d_in[17];
    const float* b3   = (const float*)d_in[18];
    float* out = (float*)d_out;

    typedef __nv_bfloat16 bf;
    bf* xh  = symaddr<bf>(g_xh);   bf* xl  = symaddr<bf>(g_xl);
    bf* qh  = symaddr<bf>(g_qh);   bf* ql  = symaddr<bf>(g_ql);
    bf* kh  = symaddr<bf>(g_kh);   bf* kl  = symaddr<bf>(g_kl);
    bf* vth = symaddr<bf>(g_vth);  bf* vtl = symaddr<bf>(g_vtl);
    bf* onh = symaddr<bf>(g_onh);  bf* onl = symaddr<bf>(g_onl);
    bf* hh  = symaddr<bf>(g_hh);   bf* hl  = symaddr<bf>(g_hl);
    bf* h2h = symaddr<bf>(g_h2h);  bf* h2l = symaddr<bf>(g_h2l);
    bf* sh_ = symaddr<bf>(g_sh);   bf* sl_ = symaddr<bf>(g_sl);
    bf* wth = symaddr<bf>(g_wth);  bf* wtl = symaddr<bf>(g_wtl);
    float* v  = symaddr<float>(g_v);
    float* tt = symaddr<float>(g_t);
    float* on = symaddr<float>(g_on);
    float* s  = symaddr<float>(g_s);

    cudaFuncSetAttribute(mma_gemm<0>, cudaFuncAttributeMaxDynamicSharedMemorySize, GEMM_SMEM);
    cudaFuncSetAttribute(mma_gemm<1>, cudaFuncAttributeMaxDynamicSharedMemorySize, GEMM_SMEM);

    const long long sSD = 2048LL * 512;
    const long long sSS = 2048LL * 2048;
    const long long WSZ = 512LL * 512;
    const float scale = 0.044194173824159216f;   // 1/sqrt(512)

    dim3 gW(16, 16, 1);
    dim3 bT(256);
    dim3 gProj(2, 128, 1);     // N=512 -> 2 tiles of 256; M=16384
    dim3 gScores(8, 16, 8);    // N=2048 -> 8; M=2048 per batch
    dim3 gAtt(2, 16, 8);

    // 1-3: inputs for q/k path
    split_kernel<<<MTOT / 1024, 256>>>(x, xh, xl, MTOT / 4);
    tsplit_kernel<<<gW, bT>>>(Wq, wth + 0 * WSZ, wtl + 0 * WSZ, 512, 512, 0, 0);
    tsplit_kernel<<<gW, bT>>>(Wk, wth + 1 * WSZ, wtl + 1 * WSZ, 512, 512, 0, 0);

    // 4-5: q, k (split out)
    mma_gemm<1><<<gProj, 256, GEMM_SMEM>>>(xh, xl, wth + 0 * WSZ, wtl + 0 * WSZ,
        bq, nullptr, qh, ql, 512, 512, 1.0f, 0, 0, 0);
    mma_gemm<1><<<gProj, 256, GEMM_SMEM>>>(xh, xl, wth + 1 * WSZ, wtl + 1 * WSZ,
        bk, nullptr, kh, kl, 512, 512, 1.0f, 0, 0, 0);

    // 6: scores = q @ k^T * scale  (LAUNCH #6 -> ncu profiles this one)
    mma_gemm<0><<<gScores, 256, GEMM_SMEM>>>(qh, ql, kh, kl,
        nullptr, s, nullptr, nullptr, 2048, 512, scale, sSD, sSD, sSS);

    // 7: softmax -> split planes
    softmax_kernel<<<16384, 256>>>(s, sh_, sl_);

    // 8-10: v path
    tsplit_kernel<<<gW, bT>>>(Wv, wth + 2 * WSZ, wtl + 2 * WSZ, 512, 512, 0, 0);
    mma_gemm<0><<<gProj, 256, GEMM_SMEM>>>(xh, xl, wth + 2 * WSZ, wtl + 2 * WSZ,
        bv, v, nullptr, nullptr, 512, 512, 1.0f, 0, 0, 0);
    tsplit_kernel<<<dim3(16, 64, 8), bT>>>(v, vth, vtl, 2048, 512, sSD, sSD);

    // 11: att = w @ v
    mma_gemm<0><<<gAtt, 256, GEMM_SMEM>>>(sh_, sl_, vth, vtl,
        nullptr, tt, nullptr, nullptr, 512, 2048, 1.0f, sSS, sSD, sSD);

    // 12: out_nxt = LN(x + att)
    rowln_kernel<0, true><<<16384, 128>>>(x, tt, ln0g, ln0b, on, onh, onl);

    // 13-15: h1
    tsplit_kernel<<<gW, bT>>>(W1, wth + 3 * WSZ, wtl + 3 * WSZ, 512, 512, 0, 0);
    mma_gemm<0><<<gProj, 256, GEMM_SMEM>>>(onh, onl, wth + 3 * WSZ, wtl + 3 * WSZ,
        b1, tt, nullptr, nullptr, 512, 512, 1.0f, 0, 0, 0);
    rowln_kernel<1, false><<<16384, 128>>>(on, tt, ln1g, ln1b, nullptr, hh, hl);

    // 16-18: h2
    tsplit_kernel<<<gW, bT>>>(W2, wth + 4 * WSZ, wtl + 4 * WSZ, 512, 512, 0, 0);
    mma_gemm<0><<<gProj, 256, GEMM_SMEM>>>(hh, hl, wth + 4 * WSZ, wtl + 4 * WSZ,
        b2, tt, nullptr, nullptr, 512, 512, 1.0f, 0, 0, 0);
    rowln_kernel<1, false><<<16384, 128>>>(on, tt, ln2g, ln2b, nullptr, h2h, h2l);

    // 19-20: out = h2 @ W3 + b3
    tsplit_kernel<<<gW, bT>>>(W3, wth + 5 * WSZ, wtl + 5 * WSZ, 512, 512, 0, 0);
    mma_gemm<0><<<gProj, 256, GEMM_SMEM>>>(h2h, h2l, wth + 5 * WSZ, wtl + 5 * WSZ,
        b3, out, nullptr, nullptr, 512, 512, 1.0f, 0, 0, 0);
}

// round 5
// speedup vs baseline: 1.1623x; 1.1623x over previous
#include <cuda_runtime.h>
#include <cuda_bf16.h>
#include <math.h>
#include <stdint.h>

// ===========================================================================
// AttentionBlock B=8,S=2048,D=512 — mma.sync bf16 3-product fp32-emulation
// R5: 128x128 tile / 64x32 warp tile / 2 CTA/SM (R3 revert) + ldmatrix
//     + scores GEMM -> split bf16 fused, softmax in-place on planes
// ===========================================================================

#define MTOT (16384 * 512)
__device__ __nv_bfloat16 g_xh[MTOT],  g_xl[MTOT];
__device__ __nv_bfloat16 g_qh[MTOT],  g_ql[MTOT];
__device__ __nv_bfloat16 g_kh[MTOT],  g_kl[MTOT];
__device__ __nv_bfloat16 g_vth[MTOT], g_vtl[MTOT];   // v^T per batch [512][2048]
__device__ __nv_bfloat16 g_onh[MTOT], g_onl[MTOT];
__device__ __nv_bfloat16 g_hh[MTOT],  g_hl[MTOT];    // h1
__device__ __nv_bfloat16 g_h2h[MTOT], g_h2l[MTOT];   // h2
__device__ __nv_bfloat16 g_sh[8LL * 2048 * 2048], g_sl[8LL * 2048 * 2048];
__device__ __nv_bfloat16 g_wth[6 * 512 * 512], g_wtl[6 * 512 * 512]; // W^T [N][K]
__device__ float g_v [MTOT];
__device__ float g_t [MTOT];
__device__ float g_on[MTOT];

// ---------------- helpers ----------------
__device__ __forceinline__ uint32_t smem_u32(const void* p) {
    uint32_t a;
    asm("{ .reg .u64 t; cvta.to.shared.u64 t, %1; cvt.u32.u64 %0, t; }"
        : "=r"(a) : "l"(p));
    return a;
}
__device__ __forceinline__ void cpa16(uint32_t dst, const void* src) {
    asm volatile("cp.async.cg.shared.global [%0], [%1], 16;"
                 :: "r"(dst), "l"(src) : "memory");
}
#define CP_COMMIT() asm volatile("cp.async.commit_group;" ::: "memory")
#define CP_WAIT1()  asm volatile("cp.async.wait_group 1;"  ::: "memory")
#define CP_WAIT0()  asm volatile("cp.async.wait_group 0;"  ::: "memory")

#define MMA_B16(c, a0, a1, a2, a3, b0, b1)                                    \
    asm volatile("mma.sync.aligned.m16n8k16.row.col.f32.bf16.bf16.f32 "       \
        "{%0,%1,%2,%3}, {%4,%5,%6,%7}, {%8,%9}, {%0,%1,%2,%3};"               \
        : "+f"((c)[0]), "+f"((c)[1]), "+f"((c)[2]), "+f"((c)[3])              \
        : "r"(a0), "r"(a1), "r"(a2), "r"(a3), "r"(b0), "r"(b1))

__device__ __forceinline__ void ldsm_x4(uint32_t& r0, uint32_t& r1,
                                        uint32_t& r2, uint32_t& r3, uint32_t a) {
    asm volatile("ldmatrix.sync.aligned.m8n8.x4.shared.b16 {%0,%1,%2,%3}, [%4];"
                 : "=r"(r0), "=r"(r1), "=r"(r2), "=r"(r3) : "r"(a));
}

// ---------------- GEMM ----------------
// Block tile 128x128, BK=32, 8 warps (2x4), warp tile 64x32, 2-stage.
// Planes per stage: Ah,Al,Bh,Bl each 128 rows * 80B = 10240B -> stage 40960B.
#define PLANE_B 10240
#define STAGE_B 40960
#define GEMM_SMEM (2 * STAGE_B)

template <int OUTM>
__global__ __launch_bounds__(256, 2) void mma_gemm(
    const __nv_bfloat16* __restrict__ Ah, const __nv_bfloat16* __restrict__ Al,
    const __nv_bfloat16* __restrict__ Bh, const __nv_bfloat16* __restrict__ Bl,
    const float* __restrict__ bias,
    float* __restrict__ Cf, __nv_bfloat16* __restrict__ Ch, __nv_bfloat16* __restrict__ Cl,
    int N, int K, float alpha,
    long long sA, long long sB, long long sC)
{
    extern __shared__ __align__(16) uint32_t sm[];
    const uint32_t sbase = smem_u32(sm);

    const int bz = blockIdx.z;
    Ah += (long long)bz * sA;  Al += (long long)bz * sA;
    Bh += (long long)bz * sB;  Bl += (long long)bz * sB;

    const int m0 = blockIdx.y * 128;
    const int n0 = blockIdx.x * 128;
    const int tid  = threadIdx.x;
    const int wid  = tid >> 5, lane = tid & 31;
    const int wm   = wid >> 2, wn = wid & 3;      // warp tile 64 x 32
    const int g    = lane >> 2, t = lane & 3;

    // loader: 2 threads per row, 2 x 16B segments each, per plane
    const int lrow = tid >> 1;
    const int lseg = (tid & 1) * 2;
    const char* gAh = (const char*)(Ah + (long long)(m0 + lrow) * K) + lseg * 16;
    const char* gAl = (const char*)(Al + (long long)(m0 + lrow) * K) + lseg * 16;
    const char* gBh = (const char*)(Bh + (long long)(n0 + lrow) * K) + lseg * 16;
    const char* gBl = (const char*)(Bl + (long long)(n0 + lrow) * K) + lseg * 16;
    const uint32_t dst0 = sbase + lrow * 80 + lseg * 16;

    // ldmatrix per-lane base offsets (within a plane)
    const uint32_t a_off = (uint32_t)(wm * 64 + (lane & 15)) * 80u
                         + (uint32_t)(lane >> 4) * 16u;
    const uint32_t b_off = (uint32_t)(wn * 32 + (lane & 7) + ((lane >> 4) & 1) * 8) * 80u
                         + (uint32_t)((lane >> 3) & 1) * 16u;

    float acc[4][4][4];
#pragma unroll
    for (int i = 0; i < 4; i++)
#pragma unroll
        for (int j = 0; j < 4; j++)
#pragma unroll
            for (int e = 0; e < 4; e++) acc[i][j][e] = 0.0f;

    const int NCH = K >> 5;

#define PREFETCH(chv) do {                                                    \
        const uint32_t so = (uint32_t)((chv) & 1) * STAGE_B;                  \
        const long long go = (long long)(chv) * 64;                           \
        cpa16(dst0 + so,               gAh + go); cpa16(dst0 + so + 16,               gAh + go + 16); \
        cpa16(dst0 + so + PLANE_B,     gAl + go); cpa16(dst0 + so + PLANE_B + 16,     gAl + go + 16); \
        cpa16(dst0 + so + 2*PLANE_B,   gBh + go); cpa16(dst0 + so + 2*PLANE_B + 16,   gBh + go + 16); \
        cpa16(dst0 + so + 3*PLANE_B,   gBl + go); cpa16(dst0 + so + 3*PLANE_B + 16,   gBl + go + 16); \
    } while (0)

    PREFETCH(0); CP_COMMIT();

    for (int ch = 0; ch < NCH; ch++) {
        if (ch + 1 < NCH) { PREFETCH(ch + 1); CP_COMMIT(); CP_WAIT1(); }
        else              { CP_WAIT0(); }
        __syncthreads();

        const uint32_t sb = sbase + (uint32_t)(ch & 1) * STAGE_B;
        const uint32_t aAh = sb + a_off;
        const uint32_t aAl = sb + PLANE_B + a_off;
        const uint32_t aBh = sb + 2 * PLANE_B + b_off;
        const uint32_t aBl = sb + 3 * PLANE_B + b_off;

#pragma unroll
        for (int ks = 0; ks < 2; ks++) {
            const uint32_t ko = ks * 32;
            uint32_t bh[4][2], bl[4][2];
            ldsm_x4(bh[0][0], bh[0][1], bh[1][0], bh[1][1], aBh + ko);
            ldsm_x4(bh[2][0], bh[2][1], bh[3][0], bh[3][1], aBh + 1280 + ko);
            ldsm_x4(bl[0][0], bl[0][1], bl[1][0], bl[1][1], aBl + ko);
            ldsm_x4(bl[2][0], bl[2][1], bl[3][0], bl[3][1], aBl + 1280 + ko);
#pragma unroll
            for (int mi = 0; mi < 4; mi++) {
                uint32_t ah[4], al[4];
                ldsm_x4(ah[0], ah[1], ah[2], ah[3], aAh + mi * 1280 + ko);
                ldsm_x4(al[0], al[1], al[2], al[3], aAl + mi * 1280 + ko);
#pragma unroll
                for (int ni = 0; ni < 4; ni++) {
                    MMA_B16(acc[mi][ni], ah[0], ah[1], ah[2], ah[3], bh[ni][0], bh[ni][1]);
                    MMA_B16(acc[mi][ni], al[0], al[1], al[2], al[3], bh[ni][0], bh[ni][1]);
                    MMA_B16(acc[mi][ni], ah[0], ah[1], ah[2], ah[3], bl[ni][0], bl[ni][1]);
                }
            }
        }
        __syncthreads();
    }

    // ---------------- epilogue ----------------
    float* CfB = Cf + (long long)bz * sC;
    __nv_bfloat16* ChB = Ch + (long long)bz * sC;
    __nv_bfloat16* ClB = Cl + (long long)bz * sC;

#pragma unroll
    for (int mi = 0; mi < 4; mi++) {
#pragma unroll
        for (int ni = 0; ni < 4; ni++) {
            const int r0 = m0 + wm * 64 + mi * 16 + g;
            const int c  = n0 + wn * 32 + ni * 8 + t * 2;
            float v0 = acc[mi][ni][0] * alpha, v1 = acc[mi][ni][1] * alpha;
            float v2 = acc[mi][ni][2] * alpha, v3 = acc[mi][ni][3] * alpha;
            if (bias) {
                const float b0 = bias[c], b1 = bias[c + 1];
                v0 += b0; v1 += b1; v2 += b0; v3 += b1;
            }
            if (OUTM == 0) {
                *(float2*)&CfB[(long long)r0 * N + c]       = make_float2(v0, v1);
                *(float2*)&CfB[(long long)(r0 + 8) * N + c] = make_float2(v2, v3);
            } else {
                __nv_bfloat162 h0 = __floats2bfloat162_rn(v0, v1);
                __nv_bfloat162 l0 = __floats2bfloat162_rn(
                    v0 - __bfloat162float(h0.x), v1 - __bfloat162float(h0.y));
                __nv_bfloat162 h1 = __floats2bfloat162_rn(v2, v3);
                __nv_bfloat162 l1 = __floats2bfloat162_rn(
                    v2 - __bfloat162float(h1.x), v3 - __bfloat162float(h1.y));
                ((__nv_bfloat162*)ChB)[((long long)r0 * N + c) >> 1]       = h0;
                ((__nv_bfloat162*)ClB)[((long long)r0 * N + c) >> 1]       = l0;
                ((__nv_bfloat162*)ChB)[((long long)(r0 + 8) * N + c) >> 1] = h1;
                ((__nv_bfloat162*)ClB)[((long long)(r0 + 8) * N + c) >> 1] = l1;
            }
        }
    }
}

// ---------------- split (fp32 -> bf16 hi/lo) ----------------
__global__ __launch_bounds__(256) void split_kernel(
    const float* __restrict__ in, __nv_bfloat16* __restrict__ oh,
    __nv_bfloat16* __restrict__ ol, int n4)
{
    const int i = blockIdx.x * 256 + threadIdx.x;
    if (i >= n4) return;
    float4 v = ((const float4*)in)[i];
    __nv_bfloat162 h0 = __floats2bfloat162_rn(v.x, v.y);
    __nv_bfloat162 h1 = __floats2bfloat162_rn(v.z, v.w);
    __nv_bfloat162 l0 = __floats2bfloat162_rn(v.x - __bfloat162float(h0.x),
                                              v.y - __bfloat162float(h0.y));
    __nv_bfloat162 l1 = __floats2bfloat162_rn(v.z - __bfloat162float(h1.x),
                                              v.w - __bfloat162float(h1.y));
    ((__nv_bfloat162*)oh)[i * 2]     = h0;
    ((__nv_bfloat162*)oh)[i * 2 + 1] = h1;
    ((__nv_bfloat162*)ol)[i * 2]     = l0;
    ((__nv_bfloat162*)ol)[i * 2 + 1] = l1;
}

// ------------- transpose + split: fp32 [R][C] -> planes [C][R] ----------
__global__ __launch_bounds__(256) void tsplit_kernel(
    const float* __restrict__ in, __nv_bfloat16* __restrict__ oh,
    __nv_bfloat16* __restrict__ ol, int R, int C,
    long long sI, long long sO)
{
    __shared__ float tile[32][33];
    const int z = blockIdx.z;
    in += (long long)z * sI;
    oh += (long long)z * sO;
    ol += (long long)z * sO;
    const int c0 = blockIdx.x * 32, r0 = blockIdx.y * 32;
    const int tx = threadIdx.x & 31, ty = threadIdx.x >> 5;

#pragma unroll
    for (int i = 0; i < 4; i++)
        tile[ty + i * 8][tx] = in[(long long)(r0 + ty + i * 8) * C + c0 + tx];
    __syncthreads();
#pragma unroll
    for (int i = 0; i < 4; i++) {
        const float v = tile[tx][ty + i * 8];
        const __nv_bfloat16 h = __float2bfloat16(v);
        const long long o = (long long)(c0 + ty + i * 8) * R + r0 + tx;
        oh[o] = h;
        ol[o] = __float2bfloat16(v - __bfloat162float(h));
    }
}

// -------- softmax, in-place on bf16 hi/lo planes (row = 2048) --------
__device__ __forceinline__ float warpMax(float v) {
#pragma unroll
    for (int o = 16; o > 0; o >>= 1) v = fmaxf(v, __shfl_xor_sync(0xffffffffu, v, o));
    return v;
}
__device__ __forceinline__ float warpSum(float v) {
#pragma unroll
    for (int o = 16; o > 0; o >>= 1) v += __shfl_xor_sync(0xffffffffu, v, o);
    return v;
}

__global__ __launch_bounds__(256) void softmax_kernel(
    __nv_bfloat16* __restrict__ H, __nv_bfloat16* __restrict__ L)
{
    const long long base = (long long)blockIdx.x * 2048;
    __nv_bfloat162* rh = (__nv_bfloat162*)(H + base);
    __nv_bfloat162* rl = (__nv_bfloat162*)(L + base);
    const int tid = threadIdx.x;
    const int lane = tid & 31, wid = tid >> 5;
    __shared__ float sh[8];

    float v[8];
#pragma unroll
    for (int j = 0; j < 4; j++) {
        const __nv_bfloat162 hv = rh[tid * 4 + j];
        const __nv_bfloat162 lv = rl[tid * 4 + j];
        v[2*j]   = __bfloat162float(hv.x) + __bfloat162float(lv.x);
        v[2*j+1] = __bfloat162float(hv.y) + __bfloat162float(lv.y);
    }

    float m = v[0];
#pragma unroll
    for (int i = 1; i < 8; i++) m = fmaxf(m, v[i]);
    m = warpMax(m);
    if (lane == 0) sh[wid] = m;
    __syncthreads();
    m = sh[0];
#pragma unroll
    for (int w = 1; w < 8; w++) m = fmaxf(m, sh[w]);

    float e[8];
    float s = 0.0f;
#pragma unroll
    for (int i = 0; i < 8; i++) { e[i] = __expf(v[i] - m); s += e[i]; }
    s = warpSum(s);
    __syncthreads();
    if (lane == 0) sh[wid] = s;
    __syncthreads();
    float tot = 0.0f;
#pragma unroll
    for (int w = 0; w < 8; w++) tot += sh[w];
    const float inv = 1.0f / tot;

#pragma unroll
    for (int j = 0; j < 4; j++) {
        const float a = e[2*j] * inv, b = e[2*j+1] * inv;
        const __nv_bfloat162 h = __floats2bfloat162_rn(a, b);
        const __nv_bfloat162 l = __floats2bfloat162_rn(
            a - __bfloat162float(h.x), b - __bfloat162float(h.y));
        rh[tid * 4 + j] = h;
        rl[tid * 4 + j] = l;
    }
}

// ---------------- fused add(+gelu)+LN ----------------
template <int MODE, bool WF32>
__global__ __launch_bounds__(128) void rowln_kernel(
    const float* __restrict__ X, const float* __restrict__ Y,
    const float* __restrict__ g, const float* __restrict__ b,
    float* __restrict__ Of, __nv_bfloat16* __restrict__ Oh,
    __nv_bfloat16* __restrict__ Ol)
{
    const long long row = (long long)blockIdx.x * 512;
    const int tid = threadIdx.x;
    const int lane = tid & 31, wid = tid >> 5;
    __shared__ float s1[4], s2[4];

    float t[4];
    float sum = 0.0f, sq = 0.0f;
#pragma unroll
    for (int i = 0; i < 4; i++) {
        const int c = tid + i * 128;
        float u = X[row + c] + Y[row + c];
        if (MODE == 1) u = 0.5f * u * (1.0f + erff(u * 0.7071067811865476f));
        t[i] = u;
        sum += u;
        sq += u * u;
    }
    sum = warpSum(sum);
    sq = warpSum(sq);
    if (lane == 0) { s1[wid] = sum; s2[wid] = sq; }
    __syncthreads();
    float ts = 0.0f, tq = 0.0f;
#pragma unroll
    for (int w = 0; w < 4; w++) { ts += s1[w]; tq += s2[w]; }
    const float mean = ts * (1.0f / 512.0f);
    const float var = tq * (1.0f / 512.0f) - mean * mean;
    const float inv = rsqrtf(var + 1e-5f);

#pragma unroll
    for (int i = 0; i < 4; i++) {
        const int c = tid + i * 128;
        const float o = (t[i] - mean) * inv * g[c] + b[c];
        if (WF32) Of[row + c] = o;
        const __nv_bfloat16 h = __float2bfloat16(o);
        Oh[row + c] = h;
        Ol[row + c] = __float2bfloat16(o - __bfloat162float(h));
    }
}

// ---------------- host ----------------
template <typename T>
static T* symaddr(const void* sym)
{
    void* p = nullptr;
    cudaGetSymbolAddress(&p, sym);
    return (T*)p;
}

extern "C" void kernel_launch(void* const* d_in, const int* in_sizes, int n_in,
                              void* d_out, int out_size)
{
    const float* x    = (const float*)d_in[0];
    const float* Wq   = (const float*)d_in[1];
    const float* bq   = (const float*)d_in[2];
    const float* Wk   = (const float*)d_in[3];
    const float* bk   = (const float*)d_in[4];
    const float* Wv   = (const float*)d_in[5];
    const float* bv   = (const float*)d_in[6];
    const float* ln0g = (const float*)d_in[7];
    const float* ln0b = (const float*)d_in[8];
    const float* W1   = (const float*)d_in[9];
    const float* b1   = (const float*)d_in[10];
    const float* ln1g = (const float*)d_in[11];
    const float* ln1b = (const float*)d_in[12];
    const float* W2   = (const float*)d_in[13];
    const float* b2   = (const float*)d_in[14];
    const float* ln2g = (const float*)d_in[15];
    const float* ln2b = (const float*)d_in[16];
    const float* W3   = (const float*)d_in[17];
    const float* b3   = (const float*)d_in[18];
    float* out = (float*)d_out;

    typedef __nv_bfloat16 bf;
    bf* xh  = symaddr<bf>(g_xh);   bf* xl  = symaddr<bf>(g_xl);
    bf* qh  = symaddr<bf>(g_qh);   bf* ql  = symaddr<bf>(g_ql);
    bf* kh  = symaddr<bf>(g_kh);   bf* kl  = symaddr<bf>(g_kl);
    bf* vth = symaddr<bf>(g_vth);  bf* vtl = symaddr<bf>(g_vtl);
    bf* onh = symaddr<bf>(g_onh);  bf* onl = symaddr<bf>(g_onl);
    bf* hh  = symaddr<bf>(g_hh);   bf* hl  = symaddr<bf>(g_hl);
    bf* h2h = symaddr<bf>(g_h2h);  bf* h2l = symaddr<bf>(g_h2l);
    bf* sh_ = symaddr<bf>(g_sh);   bf* sl_ = symaddr<bf>(g_sl);
    bf* wth = symaddr<bf>(g_wth);  bf* wtl = symaddr<bf>(g_wtl);
    float* v  = symaddr<float>(g_v);
    float* tt = symaddr<float>(g_t);
    float* on = symaddr<float>(g_on);

    cudaFuncSetAttribute(mma_gemm<0>, cudaFuncAttributeMaxDynamicSharedMemorySize, GEMM_SMEM);
    cudaFuncSetAttribute(mma_gemm<1>, cudaFuncAttributeMaxDynamicSharedMemorySize, GEMM_SMEM);

    const long long sSD = 2048LL * 512;
    const long long sSS = 2048LL * 2048;
    const long long WSZ = 512LL * 512;
    const float scale = 0.044194173824159216f;   // 1/sqrt(512)

    dim3 gW(16, 16, 1);
    dim3 bT(256);
    dim3 gProj(4, 128, 1);     // N=512, M=16384
    dim3 gScores(16, 16, 8);   // N=2048, M=2048 per batch
    dim3 gAtt(4, 16, 8);

    // 1-3: q/k path inputs
    split_kernel<<<MTOT / 1024, 256>>>(x, xh, xl, MTOT / 4);
    tsplit_kernel<<<gW, bT>>>(Wq, wth + 0 * WSZ, wtl + 0 * WSZ, 512, 512, 0, 0);
    tsplit_kernel<<<gW, bT>>>(Wk, wth + 1 * WSZ, wtl + 1 * WSZ, 512, 512, 0, 0);

    // 4-5: q, k (split out)
    mma_gemm<1><<<gProj, 256, GEMM_SMEM>>>(xh, xl, wth + 0 * WSZ, wtl + 0 * WSZ,
        bq, nullptr, qh, ql, 512, 512, 1.0f, 0, 0, 0);
    mma_gemm<1><<<gProj, 256, GEMM_SMEM>>>(xh, xl, wth + 1 * WSZ, wtl + 1 * WSZ,
        bk, nullptr, kh, kl, 512, 512, 1.0f, 0, 0, 0);

    // 6: scores = q @ k^T * scale -> split planes directly (ncu profiles this)
    mma_gemm<1><<<gScores, 256, GEMM_SMEM>>>(qh, ql, kh, kl,
        nullptr, nullptr, sh_, sl_, 2048, 512, scale, sSD, sSD, sSS);

    // 7: softmax in-place on split planes
    softmax_kernel<<<16384, 256>>>(sh_, sl_);

    // 8-10: v path
    tsplit_kernel<<<gW, bT>>>(Wv, wth + 2 * WSZ, wtl + 2 * WSZ, 512, 512, 0, 0);
    mma_gemm<0><<<gProj, 256, GEMM_SMEM>>>(xh, xl, wth + 2 * WSZ, wtl + 2 * WSZ,
        bv, v, nullptr, nullptr, 512, 512, 1.0f, 0, 0, 0);
    tsplit_kernel<<<dim3(16, 64, 8), bT>>>(v, vth, vtl, 2048, 512, sSD, sSD);

    // 11: att = w @ v
    mma_gemm<0><<<gAtt, 256, GEMM_SMEM>>>(sh_, sl_, vth, vtl,
        nullptr, tt, nullptr, nullptr, 512, 2048, 1.0f, sSS, sSD, sSD);

    // 12: out_nxt = LN(x + att)
    rowln_kernel<0, true><<<16384, 128>>>(x, tt, ln0g, ln0b, on, onh, onl);

    // 13-15: h1
    tsplit_kernel<<<gW, bT>>>(W1, wth + 3 * WSZ, wtl + 3 * WSZ, 512, 512, 0, 0);
    mma_gemm<0><<<gProj, 256, GEMM_SMEM>>>(onh, onl, wth + 3 * WSZ, wtl + 3 * WSZ,
        b1, tt, nullptr, nullptr, 512, 512, 1.0f, 0, 0, 0);
    rowln_kernel<1, false><<<16384, 128>>>(on, tt, ln1g, ln1b, nullptr, hh, hl);

    // 16-18: h2
    tsplit_kernel<<<gW, bT>>>(W2, wth + 4 * WSZ, wtl + 4 * WSZ, 512, 512, 0, 0);
    mma_gemm<0><<<gProj, 256, GEMM_SMEM>>>(hh, hl, wth + 4 * WSZ, wtl + 4 * WSZ,
        b2, tt, nullptr, nullptr, 512, 512, 1.0f, 0, 0, 0);
    rowln_kernel<1, false><<<16384, 128>>>(on, tt, ln2g, ln2b, nullptr, h2h, h2l);

    // 19-20: out = h2 @ W3 + b3
    tsplit_kernel<<<gW, bT>>>(W3, wth + 5 * WSZ, wtl + 5 * WSZ, 512, 512, 0, 0);
    mma_gemm<0><<<gProj, 256, GEMM_SMEM>>>(h2h, h2l, wth + 5 * WSZ, wtl + 5 * WSZ,
        b3, out, nullptr, nullptr, 512, 512, 1.0f, 0, 0, 0);
}

// round 6
// speedup vs baseline: 1.4598x; 1.2560x over previous
#include <cuda_runtime.h>
#include <cuda_fp16.h>
#include <math.h>
#include <stdint.h>

// ===========================================================================
// AttentionBlock B=8,S=2048,D=512 — mma.sync fp16 split-emulation
// R6: fp16 planes; NPROD=2 (A split, B rounded) on qkv/scores/att,
//     NPROD=3 on FFN GEMMs; 3-stage 1-sync pipeline for NPROD=2.
// ===========================================================================

#define MTOT (16384 * 512)
__device__ __half g_xh[MTOT],  g_xl[MTOT];
__device__ __half g_qh[MTOT],  g_ql[MTOT];
__device__ __half g_kh[MTOT];
__device__ __half g_vth[MTOT];                      // v^T per batch [512][2048], hi only
__device__ __half g_onh[MTOT], g_onl[MTOT];
__device__ __half g_hh[MTOT],  g_hl[MTOT];          // h1
__device__ __half g_h2h[MTOT], g_h2l[MTOT];         // h2
__device__ __half g_sh[8LL * 2048 * 2048], g_sl[8LL * 2048 * 2048];
__device__ __half g_wth[6 * 512 * 512], g_wtl[6 * 512 * 512]; // W^T [N][K]
__device__ float g_v [MTOT];
__device__ float g_t [MTOT];
__device__ float g_on[MTOT];

// ---------------- helpers ----------------
__device__ __forceinline__ uint32_t smem_u32(const void* p) {
    uint32_t a;
    asm("{ .reg .u64 t; cvta.to.shared.u64 t, %1; cvt.u32.u64 %0, t; }"
        : "=r"(a) : "l"(p));
    return a;
}
__device__ __forceinline__ void cpa16(uint32_t dst, const void* src) {
    asm volatile("cp.async.cg.shared.global [%0], [%1], 16;"
                 :: "r"(dst), "l"(src) : "memory");
}
#define CP_COMMIT() asm volatile("cp.async.commit_group;" ::: "memory")
#define CP_WAIT1()  asm volatile("cp.async.wait_group 1;"  ::: "memory")
#define CP_WAIT0()  asm volatile("cp.async.wait_group 0;"  ::: "memory")

#define MMA_F16(c, a0, a1, a2, a3, b0, b1)                                    \
    asm volatile("mma.sync.aligned.m16n8k16.row.col.f32.f16.f16.f32 "         \
        "{%0,%1,%2,%3}, {%4,%5,%6,%7}, {%8,%9}, {%0,%1,%2,%3};"               \
        : "+f"((c)[0]), "+f"((c)[1]), "+f"((c)[2]), "+f"((c)[3])              \
        : "r"(a0), "r"(a1), "r"(a2), "r"(a3), "r"(b0), "r"(b1))

__device__ __forceinline__ void ldsm_x4(uint32_t& r0, uint32_t& r1,
                                        uint32_t& r2, uint32_t& r3, uint32_t a) {
    asm volatile("ldmatrix.sync.aligned.m8n8.x4.shared.b16 {%0,%1,%2,%3}, [%4];"
                 : "=r"(r0), "=r"(r1), "=r"(r2), "=r"(r3) : "r"(a));
}

__device__ __forceinline__ void split2(float a, float b, __half2& h, __half2& l) {
    h = __floats2half2_rn(a, b);
    l = __floats2half2_rn(a - __half2float(h.x), b - __half2float(h.y));
}

// ---------------- GEMM ----------------
// Block tile 128x128, BK=32, 8 warps (2x4), warp tile 64x32.
// NPROD=2: planes Ah,Al,Bh -> 3-stage, 1 sync/chunk.
// NPROD=3: planes Ah,Al,Bh,Bl -> 2-stage, 2 syncs/chunk.
// OUTM: 0 = fp32 C; 1 = split hi+lo; 2 = hi only.
#define PLANE_B 10240
#define SMEM_P2 (3 * 3 * PLANE_B)   // 92160
#define SMEM_P3 (2 * 4 * PLANE_B)   // 81920

template <int NPROD, int OUTM>
__global__ __launch_bounds__(256, 2) void mma_gemm(
    const __half* __restrict__ Ah, const __half* __restrict__ Al,
    const __half* __restrict__ Bh, const __half* __restrict__ Bl,
    const float* __restrict__ bias,
    float* __restrict__ Cf, __half* __restrict__ Ch, __half* __restrict__ Cl,
    int N, int K, float alpha,
    long long sA, long long sB, long long sC)
{
    constexpr int NPLANES = (NPROD == 2) ? 3 : 4;
    constexpr int NSTG    = (NPROD == 2) ? 3 : 2;
    constexpr uint32_t STAGE = NPLANES * PLANE_B;

    extern __shared__ __align__(16) uint32_t sm[];
    const uint32_t sbase = smem_u32(sm);

    const int bz = blockIdx.z;
    Ah += (long long)bz * sA;  Al += (long long)bz * sA;
    Bh += (long long)bz * sB;
    if (NPROD == 3) Bl += (long long)bz * sB;

    const int m0 = blockIdx.y * 128;
    const int n0 = blockIdx.x * 128;
    const int tid  = threadIdx.x;
    const int wid  = tid >> 5, lane = tid & 31;
    const int wm   = wid >> 2, wn = wid & 3;      // warp tile 64 x 32
    const int g    = lane >> 2, t = lane & 3;

    // loader: 2 threads per row, 2 x 16B segments each, per plane
    const int lrow = tid >> 1;
    const int lseg = (tid & 1) * 2;
    const char* gAh = (const char*)(Ah + (long long)(m0 + lrow) * K) + lseg * 16;
    const char* gAl = (const char*)(Al + (long long)(m0 + lrow) * K) + lseg * 16;
    const char* gBh = (const char*)(Bh + (long long)(n0 + lrow) * K) + lseg * 16;
    const char* gBl = (NPROD == 3)
        ? (const char*)(Bl + (long long)(n0 + lrow) * K) + lseg * 16 : nullptr;
    const uint32_t dst0 = sbase + lrow * 80 + lseg * 16;

    // ldmatrix per-lane base offsets (within a plane)
    const uint32_t a_off = (uint32_t)(wm * 64 + (lane & 15)) * 80u
                         + (uint32_t)(lane >> 4) * 16u;
    const uint32_t b_off = (uint32_t)(wn * 32 + (lane & 7) + ((lane >> 4) & 1) * 8) * 80u
                         + (uint32_t)((lane >> 3) & 1) * 16u;

    float acc[4][4][4];
#pragma unroll
    for (int i = 0; i < 4; i++)
#pragma unroll
        for (int j = 0; j < 4; j++)
#pragma unroll
            for (int e = 0; e < 4; e++) acc[i][j][e] = 0.0f;

    const int NCH = K >> 5;

    auto PREF = [&](int chv) {
        const uint32_t so = (uint32_t)(chv % NSTG) * STAGE;
        const long long go = (long long)chv * 64;
        cpa16(dst0 + so,               gAh + go); cpa16(dst0 + so + 16,               gAh + go + 16);
        cpa16(dst0 + so + PLANE_B,     gAl + go); cpa16(dst0 + so + PLANE_B + 16,     gAl + go + 16);
        cpa16(dst0 + so + 2*PLANE_B,   gBh + go); cpa16(dst0 + so + 2*PLANE_B + 16,   gBh + go + 16);
        if (NPROD == 3) {
            cpa16(dst0 + so + 3*PLANE_B, gBl + go); cpa16(dst0 + so + 3*PLANE_B + 16, gBl + go + 16);
        }
    };

    auto COMPUTE = [&](int ch) {
        const uint32_t sb = sbase + (uint32_t)(ch % NSTG) * STAGE;
        const uint32_t aAh = sb + a_off;
        const uint32_t aAl = sb + PLANE_B + a_off;
        const uint32_t aBh = sb + 2 * PLANE_B + b_off;
        const uint32_t aBl = sb + 3 * PLANE_B + b_off;
#pragma unroll
        for (int ks = 0; ks < 2; ks++) {
            const uint32_t ko = ks * 32;
            uint32_t bh[4][2], bl[4][2];
            ldsm_x4(bh[0][0], bh[0][1], bh[1][0], bh[1][1], aBh + ko);
            ldsm_x4(bh[2][0], bh[2][1], bh[3][0], bh[3][1], aBh + 1280 + ko);
            if (NPROD == 3) {
                ldsm_x4(bl[0][0], bl[0][1], bl[1][0], bl[1][1], aBl + ko);
                ldsm_x4(bl[2][0], bl[2][1], bl[3][0], bl[3][1], aBl + 1280 + ko);
            }
#pragma unroll
            for (int mi = 0; mi < 4; mi++) {
                uint32_t ah[4], al[4];
                ldsm_x4(ah[0], ah[1], ah[2], ah[3], aAh + mi * 1280 + ko);
                ldsm_x4(al[0], al[1], al[2], al[3], aAl + mi * 1280 + ko);
#pragma unroll
                for (int ni = 0; ni < 4; ni++) {
                    MMA_F16(acc[mi][ni], ah[0], ah[1], ah[2], ah[3], bh[ni][0], bh[ni][1]);
                    MMA_F16(acc[mi][ni], al[0], al[1], al[2], al[3], bh[ni][0], bh[ni][1]);
                    if (NPROD == 3)
                        MMA_F16(acc[mi][ni], ah[0], ah[1], ah[2], ah[3], bl[ni][0], bl[ni][1]);
                }
            }
        }
    };

    if (NPROD == 2) {
        // 3-stage, 1 sync per chunk, prefetch AFTER the barrier
        PREF(0); CP_COMMIT();
        if (NCH > 1) { PREF(1); CP_COMMIT(); }
        for (int ch = 0; ch < NCH; ch++) {
            if (ch + 1 < NCH) { CP_WAIT1(); } else { CP_WAIT0(); }
            __syncthreads();
            if (ch + 2 < NCH) { PREF(ch + 2); CP_COMMIT(); }
            COMPUTE(ch);
        }
    } else {
        // 2-stage, 2 syncs per chunk
        PREF(0); CP_COMMIT();
        for (int ch = 0; ch < NCH; ch++) {
            if (ch + 1 < NCH) { PREF(ch + 1); CP_COMMIT(); CP_WAIT1(); }
            else              { CP_WAIT0(); }
            __syncthreads();
            COMPUTE(ch);
            __syncthreads();
        }
    }

    // ---------------- epilogue ----------------
    float*  CfB = Cf + (long long)bz * sC;
    __half* ChB = Ch + (long long)bz * sC;
    __half* ClB = Cl + (long long)bz * sC;

#pragma unroll
    for (int mi = 0; mi < 4; mi++) {
#pragma unroll
        for (int ni = 0; ni < 4; ni++) {
            const int r0 = m0 + wm * 64 + mi * 16 + g;
            const int c  = n0 + wn * 32 + ni * 8 + t * 2;
            float v0 = acc[mi][ni][0] * alpha, v1 = acc[mi][ni][1] * alpha;
            float v2 = acc[mi][ni][2] * alpha, v3 = acc[mi][ni][3] * alpha;
            if (bias) {
                const float b0 = bias[c], b1 = bias[c + 1];
                v0 += b0; v1 += b1; v2 += b0; v3 += b1;
            }
            if (OUTM == 0) {
                *(float2*)&CfB[(long long)r0 * N + c]       = make_float2(v0, v1);
                *(float2*)&CfB[(long long)(r0 + 8) * N + c] = make_float2(v2, v3);
            } else if (OUTM == 1) {
                __half2 h0, l0, h1, l1;
                split2(v0, v1, h0, l0);
                split2(v2, v3, h1, l1);
                ((__half2*)ChB)[((long long)r0 * N + c) >> 1]       = h0;
                ((__half2*)ClB)[((long long)r0 * N + c) >> 1]       = l0;
                ((__half2*)ChB)[((long long)(r0 + 8) * N + c) >> 1] = h1;
                ((__half2*)ClB)[((long long)(r0 + 8) * N + c) >> 1] = l1;
            } else {
                ((__half2*)ChB)[((long long)r0 * N + c) >> 1]       = __floats2half2_rn(v0, v1);
                ((__half2*)ChB)[((long long)(r0 + 8) * N + c) >> 1] = __floats2half2_rn(v2, v3);
            }
        }
    }
}

// ---------------- split (fp32 -> fp16 hi/lo) ----------------
__global__ __launch_bounds__(256) void split_kernel(
    const float* __restrict__ in, __half* __restrict__ oh,
    __half* __restrict__ ol, int n4)
{
    const int i = blockIdx.x * 256 + threadIdx.x;
    if (i >= n4) return;
    float4 v = ((const float4*)in)[i];
    __half2 h0, l0, h1, l1;
    split2(v.x, v.y, h0, l0);
    split2(v.z, v.w, h1, l1);
    ((__half2*)oh)[i * 2]     = h0;
    ((__half2*)oh)[i * 2 + 1] = h1;
    ((__half2*)ol)[i * 2]     = l0;
    ((__half2*)ol)[i * 2 + 1] = l1;
}

// ------------- transpose + split: fp32 [R][C] -> planes [C][R] ----------
__global__ __launch_bounds__(256) void tsplit_kernel(
    const float* __restrict__ in, __half* __restrict__ oh,
    __half* __restrict__ ol, int R, int C,
    long long sI, long long sO)
{
    __shared__ float tile[32][33];
    const int z = blockIdx.z;
    in += (long long)z * sI;
    oh += (long long)z * sO;
    if (ol) ol += (long long)z * sO;
    const int c0 = blockIdx.x * 32, r0 = blockIdx.y * 32;
    const int tx = threadIdx.x & 31, ty = threadIdx.x >> 5;

#pragma unroll
    for (int i = 0; i < 4; i++)
        tile[ty + i * 8][tx] = in[(long long)(r0 + ty + i * 8) * C + c0 + tx];
    __syncthreads();
#pragma unroll
    for (int i = 0; i < 4; i++) {
        const float v = tile[tx][ty + i * 8];
        const __half h = __float2half_rn(v);
        const long long o = (long long)(c0 + ty + i * 8) * R + r0 + tx;
        oh[o] = h;
        if (ol) ol[o] = __float2half_rn(v - __half2float(h));
    }
}

// -------- softmax, in-place on fp16 hi/lo planes (row = 2048) --------
__device__ __forceinline__ float warpMax(float v) {
#pragma unroll
    for (int o = 16; o > 0; o >>= 1) v = fmaxf(v, __shfl_xor_sync(0xffffffffu, v, o));
    return v;
}
__device__ __forceinline__ float warpSum(float v) {
#pragma unroll
    for (int o = 16; o > 0; o >>= 1) v += __shfl_xor_sync(0xffffffffu, v, o);
    return v;
}

__global__ __launch_bounds__(256) void softmax_kernel(
    __half* __restrict__ H, __half* __restrict__ L)
{
    const long long base = (long long)blockIdx.x * 2048;
    __half2* rh = (__half2*)(H + base);
    __half2* rl = (__half2*)(L + base);
    const int tid = threadIdx.x;
    const int lane = tid & 31, wid = tid >> 5;
    __shared__ float sh[8];

    float v[8];
#pragma unroll
    for (int j = 0; j < 4; j++) {
        const __half2 hv = rh[tid * 4 + j];
        const __half2 lv = rl[tid * 4 + j];
        v[2*j]   = __half2float(hv.x) + __half2float(lv.x);
        v[2*j+1] = __half2float(hv.y) + __half2float(lv.y);
    }

    float m = v[0];
#pragma unroll
    for (int i = 1; i < 8; i++) m = fmaxf(m, v[i]);
    m = warpMax(m);
    if (lane == 0) sh[wid] = m;
    __syncthreads();
    m = sh[0];
#pragma unroll
    for (int w = 1; w < 8; w++) m = fmaxf(m, sh[w]);

    float e[8];
    float s = 0.0f;
#pragma unroll
    for (int i = 0; i < 8; i++) { e[i] = __expf(v[i] - m); s += e[i]; }
    s = warpSum(s);
    __syncthreads();
    if (lane == 0) sh[wid] = s;
    __syncthreads();
    float tot = 0.0f;
#pragma unroll
    for (int w = 0; w < 8; w++) tot += sh[w];
    const float inv = 1.0f / tot;

#pragma unroll
    for (int j = 0; j < 4; j++) {
        __half2 h, l;
        split2(e[2*j] * inv, e[2*j+1] * inv, h, l);
        rh[tid * 4 + j] = h;
        rl[tid * 4 + j] = l;
    }
}

// ---------------- fused add(+gelu)+LN ----------------
template <int MODE, bool WF32>
__global__ __launch_bounds__(128) void rowln_kernel(
    const float* __restrict__ X, const float* __restrict__ Y,
    const float* __restrict__ g, const float* __restrict__ b,
    float* __restrict__ Of, __half* __restrict__ Oh, __half* __restrict__ Ol)
{
    const long long row = (long long)blockIdx.x * 512;
    const int tid = threadIdx.x;
    const int lane = tid & 31, wid = tid >> 5;
    __shared__ float s1[4], s2[4];

    float t[4];
    float sum = 0.0f, sq = 0.0f;
#pragma unroll
    for (int i = 0; i < 4; i++) {
        const int c = tid + i * 128;
        float u = X[row + c] + Y[row + c];
        if (MODE == 1) u = 0.5f * u * (1.0f + erff(u * 0.7071067811865476f));
        t[i] = u;
        sum += u;
        sq += u * u;
    }
    sum = warpSum(sum);
    sq = warpSum(sq);
    if (lane == 0) { s1[wid] = sum; s2[wid] = sq; }
    __syncthreads();
    float ts = 0.0f, tq = 0.0f;
#pragma unroll
    for (int w = 0; w < 4; w++) { ts += s1[w]; tq += s2[w]; }
    const float mean = ts * (1.0f / 512.0f);
    const float var = tq * (1.0f / 512.0f) - mean * mean;
    const float inv = rsqrtf(var + 1e-5f);

#pragma unroll
    for (int i = 0; i < 4; i++) {
        const int c = tid + i * 128;
        const float o = (t[i] - mean) * inv * g[c] + b[c];
        if (WF32) Of[row + c] = o;
        const __half h = __float2half_rn(o);
        Oh[row + c] = h;
        Ol[row + c] = __float2half_rn(o - __half2float(h));
    }
}

// ---------------- host ----------------
template <typename T>
static T* symaddr(const void* sym)
{
    void* p = nullptr;
    cudaGetSymbolAddress(&p, sym);
    return (T*)p;
}

extern "C" void kernel_launch(void* const* d_in, const int* in_sizes, int n_in,
                              void* d_out, int out_size)
{
    const float* x    = (const float*)d_in[0];
    const float* Wq   = (const float*)d_in[1];
    const float* bq   = (const float*)d_in[2];
    const float* Wk   = (const float*)d_in[3];
    const float* bk   = (const float*)d_in[4];
    const float* Wv   = (const float*)d_in[5];
    const float* bv   = (const float*)d_in[6];
    const float* ln0g = (const float*)d_in[7];
    const float* ln0b = (const float*)d_in[8];
    const float* W1   = (const float*)d_in[9];
    const float* b1   = (const float*)d_in[10];
    const float* ln1g = (const float*)d_in[11];
    const float* ln1b = (const float*)d_in[12];
    const float* W2   = (const float*)d_in[13];
    const float* b2   = (const float*)d_in[14];
    const float* ln2g = (const float*)d_in[15];
    const float* ln2b = (const float*)d_in[16];
    const float* W3   = (const float*)d_in[17];
    const float* b3   = (const float*)d_in[18];
    float* out = (float*)d_out;

    __half* xh  = symaddr<__half>(g_xh);   __half* xl  = symaddr<__half>(g_xl);
    __half* qh  = symaddr<__half>(g_qh);   __half* ql  = symaddr<__half>(g_ql);
    __half* kh  = symaddr<__half>(g_kh);
    __half* vth = symaddr<__half>(g_vth);
    __half* onh = symaddr<__half>(g_onh);  __half* onl = symaddr<__half>(g_onl);
    __half* hh  = symaddr<__half>(g_hh);   __half* hl  = symaddr<__half>(g_hl);
    __half* h2h = symaddr<__half>(g_h2h);  __half* h2l = symaddr<__half>(g_h2l);
    __half* sh_ = symaddr<__half>(g_sh);   __half* sl_ = symaddr<__half>(g_sl);
    __half* wth = symaddr<__half>(g_wth);  __half* wtl = symaddr<__half>(g_wtl);
    float* v  = symaddr<float>(g_v);
    float* tt = symaddr<float>(g_t);
    float* on = symaddr<float>(g_on);

    cudaFuncSetAttribute(mma_gemm<2,0>, cudaFuncAttributeMaxDynamicSharedMemorySize, SMEM_P2);
    cudaFuncSetAttribute(mma_gemm<2,1>, cudaFuncAttributeMaxDynamicSharedMemorySize, SMEM_P2);
    cudaFuncSetAttribute(mma_gemm<2,2>, cudaFuncAttributeMaxDynamicSharedMemorySize, SMEM_P2);
    cudaFuncSetAttribute(mma_gemm<3,0>, cudaFuncAttributeMaxDynamicSharedMemorySize, SMEM_P3);

    const long long sSD = 2048LL * 512;
    const long long sSS = 2048LL * 2048;
    const long long WSZ = 512LL * 512;
    const float scale = 0.044194173824159216f;   // 1/sqrt(512)

    dim3 gW(16, 16, 1);
    dim3 bT(256);
    dim3 gProj(4, 128, 1);     // N=512, M=16384
    dim3 gScores(16, 16, 8);   // N=2048, M=2048 per batch
    dim3 gAtt(4, 16, 8);

    // 1-3: q/k path inputs
    split_kernel<<<MTOT / 1024, 256>>>(x, xh, xl, MTOT / 4);
    tsplit_kernel<<<gW, bT>>>(Wq, wth + 0 * WSZ, nullptr, 512, 512, 0, 0);
    tsplit_kernel<<<gW, bT>>>(Wk, wth + 1 * WSZ, nullptr, 512, 512, 0, 0);

    // 4-5: q (split out), k (hi only)
    mma_gemm<2,1><<<gProj, 256, SMEM_P2>>>(xh, xl, wth + 0 * WSZ, nullptr,
        bq, nullptr, qh, ql, 512, 512, 1.0f, 0, 0, 0);
    mma_gemm<2,2><<<gProj, 256, SMEM_P2>>>(xh, xl, wth + 1 * WSZ, nullptr,
        bk, nullptr, kh, nullptr, 512, 512, 1.0f, 0, 0, 0);

    // 6: scores = q @ k^T * scale -> split planes  (ncu profiles this launch)
    mma_gemm<2,1><<<gScores, 256, SMEM_P2>>>(qh, ql, kh, nullptr,
        nullptr, nullptr, sh_, sl_, 2048, 512, scale, sSD, sSD, sSS);

    // 7: softmax in-place on split planes
    softmax_kernel<<<16384, 256>>>(sh_, sl_);

    // 8-10: v path
    tsplit_kernel<<<gW, bT>>>(Wv, wth + 2 * WSZ, nullptr, 512, 512, 0, 0);
    mma_gemm<2,0><<<gProj, 256, SMEM_P2>>>(xh, xl, wth + 2 * WSZ, nullptr,
        bv, v, nullptr, nullptr, 512, 512, 1.0f, 0, 0, 0);
    tsplit_kernel<<<dim3(16, 64, 8), bT>>>(v, vth, nullptr, 2048, 512, sSD, sSD);

    // 11: att = w @ v
    mma_gemm<2,0><<<gAtt, 256, SMEM_P2>>>(sh_, sl_, vth, nullptr,
        nullptr, tt, nullptr, nullptr, 512, 2048, 1.0f, sSS, sSD, sSD);

    // 12: out_nxt = LN(x + att)
    rowln_kernel<0, true><<<16384, 128>>>(x, tt, ln0g, ln0b, on, onh, onl);

    // 13-15: h1 (direct path -> NPROD=3)
    tsplit_kernel<<<gW, bT>>>(W1, wth + 3 * WSZ, wtl + 3 * WSZ, 512, 512, 0, 0);
    mma_gemm<3,0><<<gProj, 256, SMEM_P3>>>(onh, onl, wth + 3 * WSZ, wtl + 3 * WSZ,
        b1, tt, nullptr, nullptr, 512, 512, 1.0f, 0, 0, 0);
    rowln_kernel<1, false><<<16384, 128>>>(on, tt, ln1g, ln1b, nullptr, hh, hl);

    // 16-18: h2
    tsplit_kernel<<<gW, bT>>>(W2, wth + 4 * WSZ, wtl + 4 * WSZ, 512, 512, 0, 0);
    mma_gemm<3,0><<<gProj, 256, SMEM_P3>>>(hh, hl, wth + 4 * WSZ, wtl + 4 * WSZ,
        b2, tt, nullptr, nullptr, 512, 512, 1.0f, 0, 0, 0);
    rowln_kernel<1, false><<<16384, 128>>>(on, tt, ln2g, ln2b, nullptr, h2h, h2l);

    // 19-20: out = h2 @ W3 + b3
    tsplit_kernel<<<gW, bT>>>(W3, wth + 5 * WSZ, wtl + 5 * WSZ, 512, 512, 0, 0);
    mma_gemm<3,0><<<gProj, 256, SMEM_P3>>>(h2h, h2l, wth + 5 * WSZ, wtl + 5 * WSZ,
        b3, out, nullptr, nullptr, 512, 512, 1.0f, 0, 0, 0);
}

// round 7
// speedup vs baseline: 2.1678x; 1.4850x over previous
#include <cuda_runtime.h>
#include <cuda_fp16.h>
#include <math.h>
#include <stdint.h>

// ===========================================================================
// AttentionBlock B=8,S=2048,D=512 — mma.sync fp16 with precision-tiered GEMMs
// R7: NPROD=1 (pure fp16) on q/k/v/scores/att (softmax+residual attenuate),
//     NPROD=2 on W1/W2, NPROD=3 on W3. Unified 1-sync pipeline, 4-stage for
//     NPROD=1. Scores/softmax hi-only.
// ===========================================================================

#define MTOT (16384 * 512)
__device__ __half g_xh[MTOT];
__device__ __half g_qh[MTOT];
__device__ __half g_kh[MTOT];
__device__ __half g_vth[MTOT];                      // v^T per batch [512][2048]
__device__ __half g_onh[MTOT], g_onl[MTOT];
__device__ __half g_hh[MTOT],  g_hl[MTOT];          // h1
__device__ __half g_h2h[MTOT], g_h2l[MTOT];         // h2
__device__ __half g_sh[8LL * 2048 * 2048];
__device__ __half g_wth[6 * 512 * 512], g_wtl[512 * 512]; // W^T [N][K]; lo only for W3
__device__ float g_v [MTOT];
__device__ float g_t [MTOT];
__device__ float g_on[MTOT];

// ---------------- helpers ----------------
__device__ __forceinline__ uint32_t smem_u32(const void* p) {
    uint32_t a;
    asm("{ .reg .u64 t; cvta.to.shared.u64 t, %1; cvt.u32.u64 %0, t; }"
        : "=r"(a) : "l"(p));
    return a;
}
__device__ __forceinline__ void cpa16(uint32_t dst, const void* src) {
    asm volatile("cp.async.cg.shared.global [%0], [%1], 16;"
                 :: "r"(dst), "l"(src) : "memory");
}
#define CP_COMMIT() asm volatile("cp.async.commit_group;" ::: "memory")
#define CP_WAIT0()  asm volatile("cp.async.wait_group 0;"  ::: "memory")
#define CP_WAIT1()  asm volatile("cp.async.wait_group 1;"  ::: "memory")
#define CP_WAIT2()  asm volatile("cp.async.wait_group 2;"  ::: "memory")

#define MMA_F16(c, a0, a1, a2, a3, b0, b1)                                    \
    asm volatile("mma.sync.aligned.m16n8k16.row.col.f32.f16.f16.f32 "         \
        "{%0,%1,%2,%3}, {%4,%5,%6,%7}, {%8,%9}, {%0,%1,%2,%3};"               \
        : "+f"((c)[0]), "+f"((c)[1]), "+f"((c)[2]), "+f"((c)[3])              \
        : "r"(a0), "r"(a1), "r"(a2), "r"(a3), "r"(b0), "r"(b1))

__device__ __forceinline__ void ldsm_x4(uint32_t& r0, uint32_t& r1,
                                        uint32_t& r2, uint32_t& r3, uint32_t a) {
    asm volatile("ldmatrix.sync.aligned.m8n8.x4.shared.b16 {%0,%1,%2,%3}, [%4];"
                 : "=r"(r0), "=r"(r1), "=r"(r2), "=r"(r3) : "r"(a));
}

__device__ __forceinline__ void split2(float a, float b, __half2& h, __half2& l) {
    h = __floats2half2_rn(a, b);
    l = __floats2half2_rn(a - __half2float(h.x), b - __half2float(h.y));
}

// ---------------- GEMM ----------------
// Block tile 128x128, BK=32, 8 warps (2x4), warp tile 64x32.
// NPROD=1: planes [A,B],        4-stage
// NPROD=2: planes [Ah,Al,Bh],   3-stage
// NPROD=3: planes [Ah,Al,Bh,Bl] 2-stage
// OUTM: 0 = fp32 C; 1 = split hi+lo; 2 = hi only.
#define PLANE_B 10240
#define SMEM_P1 (4 * 2 * PLANE_B)   // 81920
#define SMEM_P2 (3 * 3 * PLANE_B)   // 92160
#define SMEM_P3 (2 * 4 * PLANE_B)   // 81920

template <int NPROD, int OUTM>
__global__ __launch_bounds__(256, 2) void mma_gemm(
    const __half* __restrict__ Ah, const __half* __restrict__ Al,
    const __half* __restrict__ Bh, const __half* __restrict__ Bl,
    const float* __restrict__ bias,
    float* __restrict__ Cf, __half* __restrict__ Ch, __half* __restrict__ Cl,
    int N, int K, float alpha,
    long long sA, long long sB, long long sC)
{
    constexpr int NPLANES = (NPROD == 1) ? 2 : (NPROD == 2) ? 3 : 4;
    constexpr int NSTG    = (NPROD == 1) ? 4 : (NPROD == 2) ? 3 : 2;
    constexpr uint32_t STAGE = NPLANES * PLANE_B;
    constexpr uint32_t BOFF  = (NPROD == 1) ? PLANE_B : 2 * PLANE_B;

    extern __shared__ __align__(16) uint32_t sm[];
    const uint32_t sbase = smem_u32(sm);

    const int bz = blockIdx.z;
    Ah += (long long)bz * sA;
    if (NPROD >= 2) Al += (long long)bz * sA;
    Bh += (long long)bz * sB;
    if (NPROD == 3) Bl += (long long)bz * sB;

    const int m0 = blockIdx.y * 128;
    const int n0 = blockIdx.x * 128;
    const int tid  = threadIdx.x;
    const int wid  = tid >> 5, lane = tid & 31;
    const int wm   = wid >> 2, wn = wid & 3;      // warp tile 64 x 32
    const int g    = lane >> 2, t = lane & 3;

    // loader: 2 threads per row, 2 x 16B segments each, per plane
    const int lrow = tid >> 1;
    const int lseg = (tid & 1) * 2;
    const char* gAh = (const char*)(Ah + (long long)(m0 + lrow) * K) + lseg * 16;
    const char* gAl = (NPROD >= 2)
        ? (const char*)(Al + (long long)(m0 + lrow) * K) + lseg * 16 : nullptr;
    const char* gBh = (const char*)(Bh + (long long)(n0 + lrow) * K) + lseg * 16;
    const char* gBl = (NPROD == 3)
        ? (const char*)(Bl + (long long)(n0 + lrow) * K) + lseg * 16 : nullptr;
    const uint32_t dst0 = sbase + lrow * 80 + lseg * 16;

    // ldmatrix per-lane base offsets (within a plane)
    const uint32_t a_off = (uint32_t)(wm * 64 + (lane & 15)) * 80u
                         + (uint32_t)(lane >> 4) * 16u;
    const uint32_t b_off = (uint32_t)(wn * 32 + (lane & 7) + ((lane >> 4) & 1) * 8) * 80u
                         + (uint32_t)((lane >> 3) & 1) * 16u;

    float acc[4][4][4];
#pragma unroll
    for (int i = 0; i < 4; i++)
#pragma unroll
        for (int j = 0; j < 4; j++)
#pragma unroll
            for (int e = 0; e < 4; e++) acc[i][j][e] = 0.0f;

    const int NCH = K >> 5;

    auto PREF = [&](int chv) {
        const uint32_t so = (uint32_t)(chv % NSTG) * STAGE;
        const long long go = (long long)chv * 64;
        cpa16(dst0 + so,             gAh + go); cpa16(dst0 + so + 16,             gAh + go + 16);
        if (NPROD >= 2) {
            cpa16(dst0 + so + PLANE_B, gAl + go); cpa16(dst0 + so + PLANE_B + 16, gAl + go + 16);
        }
        cpa16(dst0 + so + BOFF,      gBh + go); cpa16(dst0 + so + BOFF + 16,      gBh + go + 16);
        if (NPROD == 3) {
            cpa16(dst0 + so + 3*PLANE_B, gBl + go); cpa16(dst0 + so + 3*PLANE_B + 16, gBl + go + 16);
        }
    };

    auto COMPUTE = [&](int ch) {
        const uint32_t sb = sbase + (uint32_t)(ch % NSTG) * STAGE;
        const uint32_t aAh = sb + a_off;
        const uint32_t aAl = sb + PLANE_B + a_off;
        const uint32_t aBh = sb + BOFF + b_off;
        const uint32_t aBl = sb + 3 * PLANE_B + b_off;
#pragma unroll
        for (int ks = 0; ks < 2; ks++) {
            const uint32_t ko = ks * 32;
            uint32_t bh[4][2], bl[4][2];
            ldsm_x4(bh[0][0], bh[0][1], bh[1][0], bh[1][1], aBh + ko);
            ldsm_x4(bh[2][0], bh[2][1], bh[3][0], bh[3][1], aBh + 1280 + ko);
            if (NPROD == 3) {
                ldsm_x4(bl[0][0], bl[0][1], bl[1][0], bl[1][1], aBl + ko);
                ldsm_x4(bl[2][0], bl[2][1], bl[3][0], bl[3][1], aBl + 1280 + ko);
            }
#pragma unroll
            for (int mi = 0; mi < 4; mi++) {
                uint32_t ah[4], al[4];
                ldsm_x4(ah[0], ah[1], ah[2], ah[3], aAh + mi * 1280 + ko);
                if (NPROD >= 2)
                    ldsm_x4(al[0], al[1], al[2], al[3], aAl + mi * 1280 + ko);
#pragma unroll
                for (int ni = 0; ni < 4; ni++) {
                    MMA_F16(acc[mi][ni], ah[0], ah[1], ah[2], ah[3], bh[ni][0], bh[ni][1]);
                    if (NPROD >= 2)
                        MMA_F16(acc[mi][ni], al[0], al[1], al[2], al[3], bh[ni][0], bh[ni][1]);
                    if (NPROD == 3)
                        MMA_F16(acc[mi][ni], ah[0], ah[1], ah[2], ah[3], bl[ni][0], bl[ni][1]);
                }
            }
        }
    };

    // unified pipeline: NSTG stages, 1 sync per chunk
    {
        const int npre = (NCH < NSTG - 1) ? NCH : (NSTG - 1);
        for (int i = 0; i < npre; i++) { PREF(i); CP_COMMIT(); }
    }
    for (int ch = 0; ch < NCH; ch++) {
        int w = NSTG - 2;
        const int rem = NCH - 1 - ch;
        if (rem < w) w = rem;
        if (w <= 0)      CP_WAIT0();
        else if (w == 1) CP_WAIT1();
        else             CP_WAIT2();
        __syncthreads();
        if (ch + NSTG - 1 < NCH) { PREF(ch + NSTG - 1); CP_COMMIT(); }
        COMPUTE(ch);
    }

    // ---------------- epilogue ----------------
    float*  CfB = Cf + (long long)bz * sC;
    __half* ChB = Ch + (long long)bz * sC;
    __half* ClB = Cl + (long long)bz * sC;

#pragma unroll
    for (int mi = 0; mi < 4; mi++) {
#pragma unroll
        for (int ni = 0; ni < 4; ni++) {
            const int r0 = m0 + wm * 64 + mi * 16 + g;
            const int c  = n0 + wn * 32 + ni * 8 + t * 2;
            float v0 = acc[mi][ni][0] * alpha, v1 = acc[mi][ni][1] * alpha;
            float v2 = acc[mi][ni][2] * alpha, v3 = acc[mi][ni][3] * alpha;
            if (bias) {
                const float b0 = bias[c], b1 = bias[c + 1];
                v0 += b0; v1 += b1; v2 += b0; v3 += b1;
            }
            if (OUTM == 0) {
                *(float2*)&CfB[(long long)r0 * N + c]       = make_float2(v0, v1);
                *(float2*)&CfB[(long long)(r0 + 8) * N + c] = make_float2(v2, v3);
            } else if (OUTM == 1) {
                __half2 h0, l0, h1, l1;
                split2(v0, v1, h0, l0);
                split2(v2, v3, h1, l1);
                ((__half2*)ChB)[((long long)r0 * N + c) >> 1]       = h0;
                ((__half2*)ClB)[((long long)r0 * N + c) >> 1]       = l0;
                ((__half2*)ChB)[((long long)(r0 + 8) * N + c) >> 1] = h1;
                ((__half2*)ClB)[((long long)(r0 + 8) * N + c) >> 1] = l1;
            } else {
                ((__half2*)ChB)[((long long)r0 * N + c) >> 1]       = __floats2half2_rn(v0, v1);
                ((__half2*)ChB)[((long long)(r0 + 8) * N + c) >> 1] = __floats2half2_rn(v2, v3);
            }
        }
    }
}

// ---------------- fp32 -> fp16 ----------------
__global__ __launch_bounds__(256) void tohalf_kernel(
    const float* __restrict__ in, __half* __restrict__ oh, int n4)
{
    const int i = blockIdx.x * 256 + threadIdx.x;
    if (i >= n4) return;
    float4 v = ((const float4*)in)[i];
    ((__half2*)oh)[i * 2]     = __floats2half2_rn(v.x, v.y);
    ((__half2*)oh)[i * 2 + 1] = __floats2half2_rn(v.z, v.w);
}

// ------------- transpose (+optional split): fp32 [R][C] -> [C][R] ----------
__global__ __launch_bounds__(256) void tsplit_kernel(
    const float* __restrict__ in, __half* __restrict__ oh,
    __half* __restrict__ ol, int R, int C,
    long long sI, long long sO)
{
    __shared__ float tile[32][33];
    const int z = blockIdx.z;
    in += (long long)z * sI;
    oh += (long long)z * sO;
    if (ol) ol += (long long)z * sO;
    const int c0 = blockIdx.x * 32, r0 = blockIdx.y * 32;
    const int tx = threadIdx.x & 31, ty = threadIdx.x >> 5;

#pragma unroll
    for (int i = 0; i < 4; i++)
        tile[ty + i * 8][tx] = in[(long long)(r0 + ty + i * 8) * C + c0 + tx];
    __syncthreads();
#pragma unroll
    for (int i = 0; i < 4; i++) {
        const float v = tile[tx][ty + i * 8];
        const __half h = __float2half_rn(v);
        const long long o = (long long)(c0 + ty + i * 8) * R + r0 + tx;
        oh[o] = h;
        if (ol) ol[o] = __float2half_rn(v - __half2float(h));
    }
}

// -------- softmax, in-place on fp16 plane (row = 2048) --------
__device__ __forceinline__ float warpMax(float v) {
#pragma unroll
    for (int o = 16; o > 0; o >>= 1) v = fmaxf(v, __shfl_xor_sync(0xffffffffu, v, o));
    return v;
}
__device__ __forceinline__ float warpSum(float v) {
#pragma unroll
    for (int o = 16; o > 0; o >>= 1) v += __shfl_xor_sync(0xffffffffu, v, o);
    return v;
}

__global__ __launch_bounds__(256) void softmax_kernel(__half* __restrict__ H)
{
    const long long base = (long long)blockIdx.x * 2048;
    __half2* rh = (__half2*)(H + base);
    const int tid = threadIdx.x;
    const int lane = tid & 31, wid = tid >> 5;
    __shared__ float sh[8];

    float v[8];
#pragma unroll
    for (int j = 0; j < 4; j++) {
        const __half2 hv = rh[tid * 4 + j];
        v[2*j]   = __half2float(hv.x);
        v[2*j+1] = __half2float(hv.y);
    }

    float m = v[0];
#pragma unroll
    for (int i = 1; i < 8; i++) m = fmaxf(m, v[i]);
    m = warpMax(m);
    if (lane == 0) sh[wid] = m;
    __syncthreads();
    m = sh[0];
#pragma unroll
    for (int w = 1; w < 8; w++) m = fmaxf(m, sh[w]);

    float e[8];
    float s = 0.0f;
#pragma unroll
    for (int i = 0; i < 8; i++) { e[i] = __expf(v[i] - m); s += e[i]; }
    s = warpSum(s);
    __syncthreads();
    if (lane == 0) sh[wid] = s;
    __syncthreads();
    float tot = 0.0f;
#pragma unroll
    for (int w = 0; w < 8; w++) tot += sh[w];
    const float inv = 1.0f / tot;

#pragma unroll
    for (int j = 0; j < 4; j++)
        rh[tid * 4 + j] = __floats2half2_rn(e[2*j] * inv, e[2*j+1] * inv);
}

// ---------------- fused add(+gelu)+LN ----------------
template <int MODE, bool WF32>
__global__ __launch_bounds__(128) void rowln_kernel(
    const float* __restrict__ X, const float* __restrict__ Y,
    const float* __restrict__ g, const float* __restrict__ b,
    float* __restrict__ Of, __half* __restrict__ Oh, __half* __restrict__ Ol)
{
    const long long row = (long long)blockIdx.x * 512;
    const int tid = threadIdx.x;
    const int lane = tid & 31, wid = tid >> 5;
    __shared__ float s1[4], s2[4];

    float t[4];
    float sum = 0.0f, sq = 0.0f;
#pragma unroll
    for (int i = 0; i < 4; i++) {
        const int c = tid + i * 128;
        float u = X[row + c] + Y[row + c];
        if (MODE == 1) u = 0.5f * u * (1.0f + erff(u * 0.7071067811865476f));
        t[i] = u;
        sum += u;
        sq += u * u;
    }
    sum = warpSum(sum);
    sq = warpSum(sq);
    if (lane == 0) { s1[wid] = sum; s2[wid] = sq; }
    __syncthreads();
    float ts = 0.0f, tq = 0.0f;
#pragma unroll
    for (int w = 0; w < 4; w++) { ts += s1[w]; tq += s2[w]; }
    const float mean = ts * (1.0f / 512.0f);
    const float var = tq * (1.0f / 512.0f) - mean * mean;
    const float inv = rsqrtf(var + 1e-5f);

#pragma unroll
    for (int i = 0; i < 4; i++) {
        const int c = tid + i * 128;
        const float o = (t[i] - mean) * inv * g[c] + b[c];
        if (WF32) Of[row + c] = o;
        const __half h = __float2half_rn(o);
        Oh[row + c] = h;
        Ol[row + c] = __float2half_rn(o - __half2float(h));
    }
}

// ---------------- host ----------------
template <typename T>
static T* symaddr(const void* sym)
{
    void* p = nullptr;
    cudaGetSymbolAddress(&p, sym);
    return (T*)p;
}

extern "C" void kernel_launch(void* const* d_in, const int* in_sizes, int n_in,
                              void* d_out, int out_size)
{
    const float* x    = (const float*)d_in[0];
    const float* Wq   = (const float*)d_in[1];
    const float* bq   = (const float*)d_in[2];
    const float* Wk   = (const float*)d_in[3];
    const float* bk   = (const float*)d_in[4];
    const float* Wv   = (const float*)d_in[5];
    const float* bv   = (const float*)d_in[6];
    const float* ln0g = (const float*)d_in[7];
    const float* ln0b = (const float*)d_in[8];
    const float* W1   = (const float*)d_in[9];
    const float* b1   = (const float*)d_in[10];
    const float* ln1g = (const float*)d_in[11];
    const float* ln1b = (const float*)d_in[12];
    const float* W2   = (const float*)d_in[13];
    const float* b2   = (const float*)d_in[14];
    const float* ln2g = (const float*)d_in[15];
    const float* ln2b = (const float*)d_in[16];
    const float* W3   = (const float*)d_in[17];
    const float* b3   = (const float*)d_in[18];
    float* out = (float*)d_out;

    __half* xh  = symaddr<__half>(g_xh);
    __half* qh  = symaddr<__half>(g_qh);
    __half* kh  = symaddr<__half>(g_kh);
    __half* vth = symaddr<__half>(g_vth);
    __half* onh = symaddr<__half>(g_onh);  __half* onl = symaddr<__half>(g_onl);
    __half* hh  = symaddr<__half>(g_hh);   __half* hl  = symaddr<__half>(g_hl);
    __half* h2h = symaddr<__half>(g_h2h);  __half* h2l = symaddr<__half>(g_h2l);
    __half* sh_ = symaddr<__half>(g_sh);
    __half* wth = symaddr<__half>(g_wth);  __half* wtl = symaddr<__half>(g_wtl);
    float* v  = symaddr<float>(g_v);
    float* tt = symaddr<float>(g_t);
    float* on = symaddr<float>(g_on);

    cudaFuncSetAttribute(mma_gemm<1,0>, cudaFuncAttributeMaxDynamicSharedMemorySize, SMEM_P1);
    cudaFuncSetAttribute(mma_gemm<1,2>, cudaFuncAttributeMaxDynamicSharedMemorySize, SMEM_P1);
    cudaFuncSetAttribute(mma_gemm<2,0>, cudaFuncAttributeMaxDynamicSharedMemorySize, SMEM_P2);
    cudaFuncSetAttribute(mma_gemm<3,0>, cudaFuncAttributeMaxDynamicSharedMemorySize, SMEM_P3);

    const long long sSD = 2048LL * 512;
    const long long sSS = 2048LL * 2048;
    const long long WSZ = 512LL * 512;
    const float scale = 0.044194173824159216f;   // 1/sqrt(512)

    dim3 gW(16, 16, 1);
    dim3 bT(256);
    dim3 gProj(4, 128, 1);     // N=512, M=16384
    dim3 gScores(16, 16, 8);   // N=2048, M=2048 per batch
    dim3 gAtt(4, 16, 8);

    // 1-3: q/k path inputs
    tohalf_kernel<<<MTOT / 1024, 256>>>(x, xh, MTOT / 4);
    tsplit_kernel<<<gW, bT>>>(Wq, wth + 0 * WSZ, nullptr, 512, 512, 0, 0);
    tsplit_kernel<<<gW, bT>>>(Wk, wth + 1 * WSZ, nullptr, 512, 512, 0, 0);

    // 4-5: q, k (hi only, NPROD=1)
    mma_gemm<1,2><<<gProj, 256, SMEM_P1>>>(xh, nullptr, wth + 0 * WSZ, nullptr,
        bq, nullptr, qh, nullptr, 512, 512, 1.0f, 0, 0, 0);
    mma_gemm<1,2><<<gProj, 256, SMEM_P1>>>(xh, nullptr, wth + 1 * WSZ, nullptr,
        bk, nullptr, kh, nullptr, 512, 512, 1.0f, 0, 0, 0);

    // 6: scores = q @ k^T * scale -> fp16 (ncu profiles this launch)
    mma_gemm<1,2><<<gScores, 256, SMEM_P1>>>(qh, nullptr, kh, nullptr,
        nullptr, nullptr, sh_, nullptr, 2048, 512, scale, sSD, sSD, sSS);

    // 7: softmax in-place (hi only)
    softmax_kernel<<<16384, 256>>>(sh_);

    // 8-10: v path
    tsplit_kernel<<<gW, bT>>>(Wv, wth + 2 * WSZ, nullptr, 512, 512, 0, 0);
    mma_gemm<1,0><<<gProj, 256, SMEM_P1>>>(xh, nullptr, wth + 2 * WSZ, nullptr,
        bv, v, nullptr, nullptr, 512, 512, 1.0f, 0, 0, 0);
    tsplit_kernel<<<dim3(16, 64, 8), bT>>>(v, vth, nullptr, 2048, 512, sSD, sSD);

    // 11: att = w @ v  (NPROD=1)
    mma_gemm<1,0><<<gAtt, 256, SMEM_P1>>>(sh_, nullptr, vth, nullptr,
        nullptr, tt, nullptr, nullptr, 512, 2048, 1.0f, sSS, sSD, sSD);

    // 12: out_nxt = LN(x + att)
    rowln_kernel<0, true><<<16384, 128>>>(x, tt, ln0g, ln0b, on, onh, onl);

    // 13-15: h1 (NPROD=2: A split, W rounded)
    tsplit_kernel<<<gW, bT>>>(W1, wth + 3 * WSZ, nullptr, 512, 512, 0, 0);
    mma_gemm<2,0><<<gProj, 256, SMEM_P2>>>(onh, onl, wth + 3 * WSZ, nullptr,
        b1, tt, nullptr, nullptr, 512, 512, 1.0f, 0, 0, 0);
    rowln_kernel<1, false><<<16384, 128>>>(on, tt, ln1g, ln1b, nullptr, hh, hl);

    // 16-18: h2 (NPROD=2)
    tsplit_kernel<<<gW, bT>>>(W2, wth + 4 * WSZ, nullptr, 512, 512, 0, 0);
    mma_gemm<2,0><<<gProj, 256, SMEM_P2>>>(hh, hl, wth + 4 * WSZ, nullptr,
        b2, tt, nullptr, nullptr, 512, 512, 1.0f, 0, 0, 0);
    rowln_kernel<1, false><<<16384, 128>>>(on, tt, ln2g, ln2b, nullptr, h2h, h2l);

    // 19-20: out = h2 @ W3 + b3 (NPROD=3: undamped final GEMM)
    tsplit_kernel<<<gW, bT>>>(W3, wth + 5 * WSZ, wtl, 512, 512, 0, 0);
    mma_gemm<3,0><<<gProj, 256, SMEM_P3>>>(h2h, h2l, wth + 5 * WSZ, wtl,
        b3, out, nullptr, nullptr, 512, 512, 1.0f, 0, 0, 0);
}

// round 8
// speedup vs baseline: 2.2100x; 1.0195x over previous
#include <cuda_runtime.h>
#include <cuda_fp16.h>
#include <math.h>
#include <stdint.h>

// ===========================================================================
// AttentionBlock B=8,S=2048,D=512 — mma.sync fp16, precision-tiered GEMMs
// R8: fragment-preload pipelining in NPROD=1 mainloop; W3 demoted to NPROD=2.
// ===========================================================================

#define MTOT (16384 * 512)
__device__ __half g_xh[MTOT];
__device__ __half g_qh[MTOT];
__device__ __half g_kh[MTOT];
__device__ __half g_vth[MTOT];                      // v^T per batch [512][2048]
__device__ __half g_onh[MTOT], g_onl[MTOT];
__device__ __half g_hh[MTOT],  g_hl[MTOT];          // h1
__device__ __half g_h2h[MTOT], g_h2l[MTOT];         // h2
__device__ __half g_sh[8LL * 2048 * 2048];
__device__ __half g_wth[6 * 512 * 512];             // W^T [N][K], fp16
__device__ float g_v [MTOT];
__device__ float g_t [MTOT];
__device__ float g_on[MTOT];

// ---------------- helpers ----------------
__device__ __forceinline__ uint32_t smem_u32(const void* p) {
    uint32_t a;
    asm("{ .reg .u64 t; cvta.to.shared.u64 t, %1; cvt.u32.u64 %0, t; }"
        : "=r"(a) : "l"(p));
    return a;
}
__device__ __forceinline__ void cpa16(uint32_t dst, const void* src) {
    asm volatile("cp.async.cg.shared.global [%0], [%1], 16;"
                 :: "r"(dst), "l"(src) : "memory");
}
#define CP_COMMIT() asm volatile("cp.async.commit_group;" ::: "memory")
#define CP_WAIT0()  asm volatile("cp.async.wait_group 0;"  ::: "memory")
#define CP_WAIT1()  asm volatile("cp.async.wait_group 1;"  ::: "memory")
#define CP_WAIT2()  asm volatile("cp.async.wait_group 2;"  ::: "memory")

#define MMA_F16(c, a0, a1, a2, a3, b0, b1)                                    \
    asm volatile("mma.sync.aligned.m16n8k16.row.col.f32.f16.f16.f32 "         \
        "{%0,%1,%2,%3}, {%4,%5,%6,%7}, {%8,%9}, {%0,%1,%2,%3};"               \
        : "+f"((c)[0]), "+f"((c)[1]), "+f"((c)[2]), "+f"((c)[3])              \
        : "r"(a0), "r"(a1), "r"(a2), "r"(a3), "r"(b0), "r"(b1))

__device__ __forceinline__ void ldsm_x4(uint32_t& r0, uint32_t& r1,
                                        uint32_t& r2, uint32_t& r3, uint32_t a) {
    asm volatile("ldmatrix.sync.aligned.m8n8.x4.shared.b16 {%0,%1,%2,%3}, [%4];"
                 : "=r"(r0), "=r"(r1), "=r"(r2), "=r"(r3) : "r"(a));
}

__device__ __forceinline__ void split2(float a, float b, __half2& h, __half2& l) {
    h = __floats2half2_rn(a, b);
    l = __floats2half2_rn(a - __half2float(h.x), b - __half2float(h.y));
}

// ---------------- GEMM ----------------
// Block tile 128x128, BK=32, 8 warps (2x4), warp tile 64x32.
// NPROD=1: planes [A,B],      4-stage, fragment-preloaded mainloop
// NPROD=2: planes [Ah,Al,Bh], 3-stage
// OUTM: 0 = fp32 C; 1 = split hi+lo; 2 = hi only.
#define PLANE_B 10240
#define SMEM_P1 (4 * 2 * PLANE_B)   // 81920
#define SMEM_P2 (3 * 3 * PLANE_B)   // 92160

template <int NPROD, int OUTM>
__global__ __launch_bounds__(256, 2) void mma_gemm(
    const __half* __restrict__ Ah, const __half* __restrict__ Al,
    const __half* __restrict__ Bh,
    const float* __restrict__ bias,
    float* __restrict__ Cf, __half* __restrict__ Ch, __half* __restrict__ Cl,
    int N, int K, float alpha,
    long long sA, long long sB, long long sC)
{
    constexpr int NPLANES = (NPROD == 1) ? 2 : 3;
    constexpr int NSTG    = (NPROD == 1) ? 4 : 3;
    constexpr uint32_t STAGE = NPLANES * PLANE_B;
    constexpr uint32_t BOFF  = (NPROD == 1) ? PLANE_B : 2 * PLANE_B;

    extern __shared__ __align__(16) uint32_t sm[];
    const uint32_t sbase = smem_u32(sm);

    const int bz = blockIdx.z;
    Ah += (long long)bz * sA;
    if (NPROD >= 2) Al += (long long)bz * sA;
    Bh += (long long)bz * sB;

    const int m0 = blockIdx.y * 128;
    const int n0 = blockIdx.x * 128;
    const int tid  = threadIdx.x;
    const int wid  = tid >> 5, lane = tid & 31;
    const int wm   = wid >> 2, wn = wid & 3;      // warp tile 64 x 32
    const int g    = lane >> 2, t = lane & 3;

    // loader: 2 threads per row, 2 x 16B segments each, per plane
    const int lrow = tid >> 1;
    const int lseg = (tid & 1) * 2;
    const char* gAh = (const char*)(Ah + (long long)(m0 + lrow) * K) + lseg * 16;
    const char* gAl = (NPROD >= 2)
        ? (const char*)(Al + (long long)(m0 + lrow) * K) + lseg * 16 : nullptr;
    const char* gBh = (const char*)(Bh + (long long)(n0 + lrow) * K) + lseg * 16;
    const uint32_t dst0 = sbase + lrow * 80 + lseg * 16;

    // ldmatrix per-lane base offsets (within a plane)
    const uint32_t a_off = (uint32_t)(wm * 64 + (lane & 15)) * 80u
                         + (uint32_t)(lane >> 4) * 16u;
    const uint32_t b_off = (uint32_t)(wn * 32 + (lane & 7) + ((lane >> 4) & 1) * 8) * 80u
                         + (uint32_t)((lane >> 3) & 1) * 16u;

    float acc[4][4][4];
#pragma unroll
    for (int i = 0; i < 4; i++)
#pragma unroll
        for (int j = 0; j < 4; j++)
#pragma unroll
            for (int e = 0; e < 4; e++) acc[i][j][e] = 0.0f;

    const int NCH = K >> 5;

    auto PREF = [&](int chv) {
        const uint32_t so = (uint32_t)(chv % NSTG) * STAGE;
        const long long go = (long long)chv * 64;
        cpa16(dst0 + so,             gAh + go); cpa16(dst0 + so + 16,             gAh + go + 16);
        if (NPROD >= 2) {
            cpa16(dst0 + so + PLANE_B, gAl + go); cpa16(dst0 + so + PLANE_B + 16, gAl + go + 16);
        }
        cpa16(dst0 + so + BOFF,      gBh + go); cpa16(dst0 + so + BOFF + 16,      gBh + go + 16);
    };

    auto COMPUTE = [&](int ch) {
        const uint32_t sb = sbase + (uint32_t)(ch % NSTG) * STAGE;
        if (NPROD == 1) {
            // preload ALL fragments for the chunk, then issue all 32 MMAs
            const uint32_t aA = sb + a_off;
            const uint32_t aB = sb + BOFF + b_off;
            uint32_t bf[2][4][2], af[2][4][4];
#pragma unroll
            for (int ks = 0; ks < 2; ks++) {
                const uint32_t ko = ks * 32;
                ldsm_x4(bf[ks][0][0], bf[ks][0][1], bf[ks][1][0], bf[ks][1][1], aB + ko);
                ldsm_x4(bf[ks][2][0], bf[ks][2][1], bf[ks][3][0], bf[ks][3][1], aB + 1280 + ko);
#pragma unroll
                for (int mi = 0; mi < 4; mi++)
                    ldsm_x4(af[ks][mi][0], af[ks][mi][1], af[ks][mi][2], af[ks][mi][3],
                            aA + mi * 1280 + ko);
            }
#pragma unroll
            for (int ks = 0; ks < 2; ks++)
#pragma unroll
                for (int mi = 0; mi < 4; mi++)
#pragma unroll
                    for (int ni = 0; ni < 4; ni++)
                        MMA_F16(acc[mi][ni],
                                af[ks][mi][0], af[ks][mi][1], af[ks][mi][2], af[ks][mi][3],
                                bf[ks][ni][0], bf[ks][ni][1]);
        } else {
            const uint32_t aAh = sb + a_off;
            const uint32_t aAl = sb + PLANE_B + a_off;
            const uint32_t aBh = sb + BOFF + b_off;
#pragma unroll
            for (int ks = 0; ks < 2; ks++) {
                const uint32_t ko = ks * 32;
                uint32_t bh[4][2];
                ldsm_x4(bh[0][0], bh[0][1], bh[1][0], bh[1][1], aBh + ko);
                ldsm_x4(bh[2][0], bh[2][1], bh[3][0], bh[3][1], aBh + 1280 + ko);
#pragma unroll
                for (int mi = 0; mi < 4; mi++) {
                    uint32_t ah[4], al[4];
                    ldsm_x4(ah[0], ah[1], ah[2], ah[3], aAh + mi * 1280 + ko);
                    ldsm_x4(al[0], al[1], al[2], al[3], aAl + mi * 1280 + ko);
#pragma unroll
                    for (int ni = 0; ni < 4; ni++) {
                        MMA_F16(acc[mi][ni], ah[0], ah[1], ah[2], ah[3], bh[ni][0], bh[ni][1]);
                        MMA_F16(acc[mi][ni], al[0], al[1], al[2], al[3], bh[ni][0], bh[ni][1]);
                    }
                }
            }
        }
    };

    // pipeline: NSTG stages, 1 sync per chunk
    {
        const int npre = (NCH < NSTG - 1) ? NCH : (NSTG - 1);
        for (int i = 0; i < npre; i++) { PREF(i); CP_COMMIT(); }
    }
    for (int ch = 0; ch < NCH; ch++) {
        int w = NSTG - 2;
        const int rem = NCH - 1 - ch;
        if (rem < w) w = rem;
        if (w <= 0)      CP_WAIT0();
        else if (w == 1) CP_WAIT1();
        else             CP_WAIT2();
        __syncthreads();
        if (ch + NSTG - 1 < NCH) { PREF(ch + NSTG - 1); CP_COMMIT(); }
        COMPUTE(ch);
    }

    // ---------------- epilogue ----------------
    float*  CfB = Cf + (long long)bz * sC;
    __half* ChB = Ch + (long long)bz * sC;
    __half* ClB = Cl + (long long)bz * sC;

#pragma unroll
    for (int mi = 0; mi < 4; mi++) {
#pragma unroll
        for (int ni = 0; ni < 4; ni++) {
            const int r0 = m0 + wm * 64 + mi * 16 + g;
            const int c  = n0 + wn * 32 + ni * 8 + t * 2;
            float v0 = acc[mi][ni][0] * alpha, v1 = acc[mi][ni][1] * alpha;
            float v2 = acc[mi][ni][2] * alpha, v3 = acc[mi][ni][3] * alpha;
            if (bias) {
                const float b0 = bias[c], b1 = bias[c + 1];
                v0 += b0; v1 += b1; v2 += b0; v3 += b1;
            }
            if (OUTM == 0) {
                *(float2*)&CfB[(long long)r0 * N + c]       = make_float2(v0, v1);
                *(float2*)&CfB[(long long)(r0 + 8) * N + c] = make_float2(v2, v3);
            } else if (OUTM == 1) {
                __half2 h0, l0, h1, l1;
                split2(v0, v1, h0, l0);
                split2(v2, v3, h1, l1);
                ((__half2*)ChB)[((long long)r0 * N + c) >> 1]       = h0;
                ((__half2*)ClB)[((long long)r0 * N + c) >> 1]       = l0;
                ((__half2*)ChB)[((long long)(r0 + 8) * N + c) >> 1] = h1;
                ((__half2*)ClB)[((long long)(r0 + 8) * N + c) >> 1] = l1;
            } else {
                ((__half2*)ChB)[((long long)r0 * N + c) >> 1]       = __floats2half2_rn(v0, v1);
                ((__half2*)ChB)[((long long)(r0 + 8) * N + c) >> 1] = __floats2half2_rn(v2, v3);
            }
        }
    }
}

// ---------------- fp32 -> fp16 ----------------
__global__ __launch_bounds__(256) void tohalf_kernel(
    const float* __restrict__ in, __half* __restrict__ oh, int n4)
{
    const int i = blockIdx.x * 256 + threadIdx.x;
    if (i >= n4) return;
    float4 v = ((const float4*)in)[i];
    ((__half2*)oh)[i * 2]     = __floats2half2_rn(v.x, v.y);
    ((__half2*)oh)[i * 2 + 1] = __floats2half2_rn(v.z, v.w);
}

// ------------- transpose: fp32 [R][C] -> fp16 [C][R] ----------
__global__ __launch_bounds__(256) void tsplit_kernel(
    const float* __restrict__ in, __half* __restrict__ oh,
    int R, int C, long long sI, long long sO)
{
    __shared__ float tile[32][33];
    const int z = blockIdx.z;
    in += (long long)z * sI;
    oh += (long long)z * sO;
    const int c0 = blockIdx.x * 32, r0 = blockIdx.y * 32;
    const int tx = threadIdx.x & 31, ty = threadIdx.x >> 5;

#pragma unroll
    for (int i = 0; i < 4; i++)
        tile[ty + i * 8][tx] = in[(long long)(r0 + ty + i * 8) * C + c0 + tx];
    __syncthreads();
#pragma unroll
    for (int i = 0; i < 4; i++) {
        const float v = tile[tx][ty + i * 8];
        oh[(long long)(c0 + ty + i * 8) * R + r0 + tx] = __float2half_rn(v);
    }
}

// -------- softmax, in-place on fp16 plane (row = 2048) --------
__device__ __forceinline__ float warpMax(float v) {
#pragma unroll
    for (int o = 16; o > 0; o >>= 1) v = fmaxf(v, __shfl_xor_sync(0xffffffffu, v, o));
    return v;
}
__device__ __forceinline__ float warpSum(float v) {
#pragma unroll
    for (int o = 16; o > 0; o >>= 1) v += __shfl_xor_sync(0xffffffffu, v, o);
    return v;
}

__global__ __launch_bounds__(256) void softmax_kernel(__half* __restrict__ H)
{
    const long long base = (long long)blockIdx.x * 2048;
    __half2* rh = (__half2*)(H + base);
    const int tid = threadIdx.x;
    const int lane = tid & 31, wid = tid >> 5;
    __shared__ float sh[8];

    float v[8];
#pragma unroll
    for (int j = 0; j < 4; j++) {
        const __half2 hv = rh[tid * 4 + j];
        v[2*j]   = __half2float(hv.x);
        v[2*j+1] = __half2float(hv.y);
    }

    float m = v[0];
#pragma unroll
    for (int i = 1; i < 8; i++) m = fmaxf(m, v[i]);
    m = warpMax(m);
    if (lane == 0) sh[wid] = m;
    __syncthreads();
    m = sh[0];
#pragma unroll
    for (int w = 1; w < 8; w++) m = fmaxf(m, sh[w]);

    float e[8];
    float s = 0.0f;
#pragma unroll
    for (int i = 0; i < 8; i++) { e[i] = __expf(v[i] - m); s += e[i]; }
    s = warpSum(s);
    __syncthreads();
    if (lane == 0) sh[wid] = s;
    __syncthreads();
    float tot = 0.0f;
#pragma unroll
    for (int w = 0; w < 8; w++) tot += sh[w];
    const float inv = 1.0f / tot;

#pragma unroll
    for (int j = 0; j < 4; j++)
        rh[tid * 4 + j] = __floats2half2_rn(e[2*j] * inv, e[2*j+1] * inv);
}

// ---------------- fused add(+gelu)+LN ----------------
template <int MODE, bool WF32>
__global__ __launch_bounds__(128) void rowln_kernel(
    const float* __restrict__ X, const float* __restrict__ Y,
    const float* __restrict__ g, const float* __restrict__ b,
    float* __restrict__ Of, __half* __restrict__ Oh, __half* __restrict__ Ol)
{
    const long long row = (long long)blockIdx.x * 512;
    const int tid = threadIdx.x;
    const int lane = tid & 31, wid = tid >> 5;
    __shared__ float s1[4], s2[4];

    float t[4];
    float sum = 0.0f, sq = 0.0f;
#pragma unroll
    for (int i = 0; i < 4; i++) {
        const int c = tid + i * 128;
        float u = X[row + c] + Y[row + c];
        if (MODE == 1) u = 0.5f * u * (1.0f + erff(u * 0.7071067811865476f));
        t[i] = u;
        sum += u;
        sq += u * u;
    }
    sum = warpSum(sum);
    sq = warpSum(sq);
    if (lane == 0) { s1[wid] = sum; s2[wid] = sq; }
    __syncthreads();
    float ts = 0.0f, tq = 0.0f;
#pragma unroll
    for (int w = 0; w < 4; w++) { ts += s1[w]; tq += s2[w]; }
    const float mean = ts * (1.0f / 512.0f);
    const float var = tq * (1.0f / 512.0f) - mean * mean;
    const float inv = rsqrtf(var + 1e-5f);

#pragma unroll
    for (int i = 0; i < 4; i++) {
        const int c = tid + i * 128;
        const float o = (t[i] - mean) * inv * g[c] + b[c];
        if (WF32) Of[row + c] = o;
        const __half h = __float2half_rn(o);
        Oh[row + c] = h;
        Ol[row + c] = __float2half_rn(o - __half2float(h));
    }
}

// ---------------- host ----------------
template <typename T>
static T* symaddr(const void* sym)
{
    void* p = nullptr;
    cudaGetSymbolAddress(&p, sym);
    return (T*)p;
}

extern "C" void kernel_launch(void* const* d_in, const int* in_sizes, int n_in,
                              void* d_out, int out_size)
{
    const float* x    = (const float*)d_in[0];
    const float* Wq   = (const float*)d_in[1];
    const float* bq   = (const float*)d_in[2];
    const float* Wk   = (const float*)d_in[3];
    const float* bk   = (const float*)d_in[4];
    const float* Wv   = (const float*)d_in[5];
    const float* bv   = (const float*)d_in[6];
    const float* ln0g = (const float*)d_in[7];
    const float* ln0b = (const float*)d_in[8];
    const float* W1   = (const float*)d_in[9];
    const float* b1   = (const float*)d_in[10];
    const float* ln1g = (const float*)d_in[11];
    const float* ln1b = (const float*)d_in[12];
    const float* W2   = (const float*)d_in[13];
    const float* b2   = (const float*)d_in[14];
    const float* ln2g = (const float*)d_in[15];
    const float* ln2b = (const float*)d_in[16];
    const float* W3   = (const float*)d_in[17];
    const float* b3   = (const float*)d_in[18];
    float* out = (float*)d_out;

    __half* xh  = symaddr<__half>(g_xh);
    __half* qh  = symaddr<__half>(g_qh);
    __half* kh  = symaddr<__half>(g_kh);
    __half* vth = symaddr<__half>(g_vth);
    __half* onh = symaddr<__half>(g_onh);  __half* onl = symaddr<__half>(g_onl);
    __half* hh  = symaddr<__half>(g_hh);   __half* hl  = symaddr<__half>(g_hl);
    __half* h2h = symaddr<__half>(g_h2h);  __half* h2l = symaddr<__half>(g_h2l);
    __half* sh_ = symaddr<__half>(g_sh);
    __half* wth = symaddr<__half>(g_wth);
    float* v  = symaddr<float>(g_v);
    float* tt = symaddr<float>(g_t);
    float* on = symaddr<float>(g_on);

    cudaFuncSetAttribute(mma_gemm<1,0>, cudaFuncAttributeMaxDynamicSharedMemorySize, SMEM_P1);
    cudaFuncSetAttribute(mma_gemm<1,2>, cudaFuncAttributeMaxDynamicSharedMemorySize, SMEM_P1);
    cudaFuncSetAttribute(mma_gemm<2,0>, cudaFuncAttributeMaxDynamicSharedMemorySize, SMEM_P2);

    const long long sSD = 2048LL * 512;
    const long long sSS = 2048LL * 2048;
    const long long WSZ = 512LL * 512;
    const float scale = 0.044194173824159216f;   // 1/sqrt(512)

    dim3 gW(16, 16, 1);
    dim3 bT(256);
    dim3 gProj(4, 128, 1);     // N=512, M=16384
    dim3 gScores(16, 16, 8);   // N=2048, M=2048 per batch
    dim3 gAtt(4, 16, 8);

    // 1-3: q/k path inputs
    tohalf_kernel<<<MTOT / 1024, 256>>>(x, xh, MTOT / 4);
    tsplit_kernel<<<gW, bT>>>(Wq, wth + 0 * WSZ, 512, 512, 0, 0);
    tsplit_kernel<<<gW, bT>>>(Wk, wth + 1 * WSZ, 512, 512, 0, 0);

    // 4-5: q, k (hi only, NPROD=1)
    mma_gemm<1,2><<<gProj, 256, SMEM_P1>>>(xh, nullptr, wth + 0 * WSZ,
        bq, nullptr, qh, nullptr, 512, 512, 1.0f, 0, 0, 0);
    mma_gemm<1,2><<<gProj, 256, SMEM_P1>>>(xh, nullptr, wth + 1 * WSZ,
        bk, nullptr, kh, nullptr, 512, 512, 1.0f, 0, 0, 0);

    // 6: scores = q @ k^T * scale -> fp16 (ncu profiles this launch)
    mma_gemm<1,2><<<gScores, 256, SMEM_P1>>>(qh, nullptr, kh,
        nullptr, nullptr, sh_, nullptr, 2048, 512, scale, sSD, sSD, sSS);

    // 7: softmax in-place
    softmax_kernel<<<16384, 256>>>(sh_);

    // 8-10: v path
    tsplit_kernel<<<gW, bT>>>(Wv, wth + 2 * WSZ, 512, 512, 0, 0);
    mma_gemm<1,0><<<gProj, 256, SMEM_P1>>>(xh, nullptr, wth + 2 * WSZ,
        bv, v, nullptr, nullptr, 512, 512, 1.0f, 0, 0, 0);
    tsplit_kernel<<<dim3(16, 64, 8), bT>>>(v, vth, 2048, 512, sSD, sSD);

    // 11: att = w @ v  (NPROD=1)
    mma_gemm<1,0><<<gAtt, 256, SMEM_P1>>>(sh_, nullptr, vth,
        nullptr, tt, nullptr, nullptr, 512, 2048, 1.0f, sSS, sSD, sSD);

    // 12: out_nxt = LN(x + att)
    rowln_kernel<0, true><<<16384, 128>>>(x, tt, ln0g, ln0b, on, onh, onl);

    // 13-15: h1 (NPROD=2: A split, W rounded)
    tsplit_kernel<<<gW, bT>>>(W1, wth + 3 * WSZ, 512, 512, 0, 0);
    mma_gemm<2,0><<<gProj, 256, SMEM_P2>>>(onh, onl, wth + 3 * WSZ,
        b1, tt, nullptr, nullptr, 512, 512, 1.0f, 0, 0, 0);
    rowln_kernel<1, false><<<16384, 128>>>(on, tt, ln1g, ln1b, nullptr, hh, hl);

    // 16-18: h2 (NPROD=2)
    tsplit_kernel<<<gW, bT>>>(W2, wth + 4 * WSZ, 512, 512, 0, 0);
    mma_gemm<2,0><<<gProj, 256, SMEM_P2>>>(hh, hl, wth + 4 * WSZ,
        b2, tt, nullptr, nullptr, 512, 512, 1.0f, 0, 0, 0);
    rowln_kernel<1, false><<<16384, 128>>>(on, tt, ln2g, ln2b, nullptr, h2h, h2l);

    // 19-20: out = h2 @ W3 + b3 (NPROD=2)
    tsplit_kernel<<<gW, bT>>>(W3, wth + 5 * WSZ, 512, 512, 0, 0);
    mma_gemm<2,0><<<gProj, 256, SMEM_P2>>>(h2h, h2l, wth + 5 * WSZ,
        b3, out, nullptr, nullptr, 512, 512, 1.0f, 0, 0, 0);
}